// round 4
// baseline (speedup 1.0000x reference)
#include <cuda_runtime.h>
#include <math.h>

// Problem constants
#define BB 4
#define LS 1024
#define DMOD 1024
#define NH 16
#define DKH 64
#define DVH 64
#define ZH (BB * NH)

#define OUT_ELEMS ((long long)BB * LS * DMOD)            // 4194304
#define ATT_ELEMS ((long long)ZH * LS * LS)              // 67108864

// -------------------- scratch (device globals; no allocation allowed) ------
__device__ float g_qh[ZH * LS * DKH];        // [B,H,L,DK]
__device__ float g_kh[ZH * LS * DKH];
__device__ float g_vh[ZH * LS * DVH];
__device__ float g_ctx[BB * LS * NH * DVH];  // [B,L,H*DV]
__device__ float g_fc[BB * LS * DMOD];       // pre-LN fc output
__device__ float g_attn[(size_t)ZH * LS * LS]; // attn scratch (fallback)
__device__ float g_outs[BB * LS * DMOD];     // fallback out sink

// ---------------------------------------------------------------------------
// helpers: tf32 convert + m16n8k8 tf32 mma
// ---------------------------------------------------------------------------
__device__ __forceinline__ unsigned f2tf(float f) {
    unsigned r;
    asm("cvt.rna.tf32.f32 %0, %1;" : "=r"(r) : "f"(f));
    return r;
}

__device__ __forceinline__ void mma8(float& c0, float& c1, float& c2, float& c3,
                                     unsigned a0, unsigned a1, unsigned a2, unsigned a3,
                                     unsigned b0, unsigned b1) {
    asm volatile(
        "mma.sync.aligned.m16n8k8.row.col.f32.tf32.tf32.f32 "
        "{%0,%1,%2,%3}, {%4,%5,%6,%7}, {%8,%9}, {%0,%1,%2,%3};\n"
        : "+f"(c0), "+f"(c1), "+f"(c2), "+f"(c3)
        : "r"(a0), "r"(a1), "r"(a2), "r"(a3), "r"(b0), "r"(b1));
}

// ---------------------------------------------------------------------------
// TF32 NT GEMM + bias:  C[r,n] = sum_k A[r,k] * W[n,k] + bias[n]
// Block tile 128x128, BK=32, 8 warps (2m x 4n), warp tile 64x32.
// ---------------------------------------------------------------------------
__global__ void __launch_bounds__(256)
gemm_tf32(const float* __restrict__ A, const float* __restrict__ W,
          const float* __restrict__ bias, float* __restrict__ out,
          int K, int N, int Dhead)
{
    __shared__ unsigned As[128 * 36];
    __shared__ unsigned Ws[128 * 36];

    const int t = threadIdx.x, lane = t & 31, w = t >> 5;
    const int wm = w >> 2, wn = w & 3;          // 2 x 4 warps
    const int g = lane >> 2, tg = lane & 3;
    const int rowBase = blockIdx.y * 128;
    const int colBase = blockIdx.x * 128;

    float c[4][4][4];
#pragma unroll
    for (int mt = 0; mt < 4; mt++)
#pragma unroll
        for (int nt = 0; nt < 4; nt++)
#pragma unroll
            for (int i = 0; i < 4; i++) c[mt][nt][i] = 0.f;

    for (int k0 = 0; k0 < K; k0 += 32) {
#pragma unroll
        for (int i = 0; i < 4; i++) {
            const int idx = t + 256 * i;
            const int row = idx >> 3, c4 = (idx & 7) * 4;
            float4 av = *(const float4*)(A + (size_t)(rowBase + row) * K + k0 + c4);
            *(uint4*)&As[row * 36 + c4] = make_uint4(f2tf(av.x), f2tf(av.y), f2tf(av.z), f2tf(av.w));
            float4 wv = *(const float4*)(W + (size_t)(colBase + row) * K + k0 + c4);
            *(uint4*)&Ws[row * 36 + c4] = make_uint4(f2tf(wv.x), f2tf(wv.y), f2tf(wv.z), f2tf(wv.w));
        }
        __syncthreads();
#pragma unroll
        for (int ks = 0; ks < 4; ks++) {
            const int kk = ks * 8;
            unsigned a[4][4], b[4][2];
#pragma unroll
            for (int mt = 0; mt < 4; mt++) {
                const int r = (wm * 64 + mt * 16 + g) * 36 + kk + tg;
                a[mt][0] = As[r];            a[mt][1] = As[r + 8 * 36];
                a[mt][2] = As[r + 4];        a[mt][3] = As[r + 8 * 36 + 4];
            }
#pragma unroll
            for (int nt = 0; nt < 4; nt++) {
                const int r = (wn * 32 + nt * 8 + g) * 36 + kk + tg;
                b[nt][0] = Ws[r];            b[nt][1] = Ws[r + 4];
            }
#pragma unroll
            for (int mt = 0; mt < 4; mt++)
#pragma unroll
                for (int nt = 0; nt < 4; nt++)
                    mma8(c[mt][nt][0], c[mt][nt][1], c[mt][nt][2], c[mt][nt][3],
                         a[mt][0], a[mt][1], a[mt][2], a[mt][3],
                         b[nt][0], b[nt][1]);
        }
        __syncthreads();
    }

    const int H = N / Dhead;
#pragma unroll
    for (int mt = 0; mt < 4; mt++) {
        const int rr = rowBase + wm * 64 + mt * 16 + g;
        const int b_ = rr >> 10, l = rr & 1023;
#pragma unroll
        for (int nt = 0; nt < 4; nt++) {
            const int cc = colBase + wn * 32 + nt * 8 + 2 * tg;
            const int h = cc / Dhead, d = cc % Dhead;
            const size_t dst = (((size_t)(b_ * H + h)) * LS + l) * Dhead + d;
            const float b0 = bias[cc], b1 = bias[cc + 1];
            *(float2*)&out[dst]             = make_float2(c[mt][nt][0] + b0, c[mt][nt][1] + b1);
            *(float2*)&out[dst + 8 * Dhead] = make_float2(c[mt][nt][2] + b0, c[mt][nt][3] + b1);
        }
    }
}

// ---------------------------------------------------------------------------
// Fused attention: per CTA = (head z, 32 q-rows).
//   Phase 1: loop 8 K-tiles of 128: S = Q K^T (tf32 MMA), gate*scale, mask,
//            exp -> smem P (32 x 1024 fp32), accumulate row sums.
//   Phase 2: invsum; write normalized attn ONCE (coalesced float4).
//   Phase 3: O = P @ V (tf32 MMA from smem), scale by invsum -> ctx.
// Block 256 threads (8 warps), grid (32, 64).
// ---------------------------------------------------------------------------
#define FROWS 32
#define PSTR  1036   // P row stride in floats (conflict-free A-frag loads)
#define KSTR  72     // K/V tile row stride
#define QSTR  68

#define SMEM_WORDS_QK (FROWS * QSTR + 2 * 128 * KSTR)
#define FUSED_SMEM_BYTES (SMEM_WORDS_QK * 4 + FROWS * PSTR * 4 + (4 * FROWS + FROWS) * 4)

__global__ void __launch_bounds__(256)
fused_attn(const float* __restrict__ qh, const float* __restrict__ kh,
           const float* __restrict__ vh, const float* __restrict__ gate,
           const int* __restrict__ mask, float* __restrict__ attn,
           float* __restrict__ ctx)
{
    extern __shared__ char smem_raw[];
    unsigned* Qs  = (unsigned*)smem_raw;             // 32 x 68
    unsigned* Ks  = Qs + FROWS * QSTR;               // 2 x (128 x 72)
    float*    P   = (float*)(Ks + 2 * 128 * KSTR);   // 32 x 1036
    float*    red = P + FROWS * PSTR;                // 4 x 32
    float*    invs = red + 4 * FROWS;                // 32

    const int t = threadIdx.x, lane = t & 31, w = t >> 5;
    const int wm = w >> 2, wn = w & 3;     // 2 x 4 warps
    const int g = lane >> 2, tg = lane & 3;
    const int z = blockIdx.y, b = z >> 4, h = z & 15;
    const int rowBase = blockIdx.x * FROWS;
    const int r0 = wm * 16 + g;

    const float* Q  = qh + (size_t)z * LS * DKH + (size_t)rowBase * DKH;
    const float* Kp = kh + (size_t)z * LS * DKH;
    const float* V  = vh + (size_t)z * LS * DVH;

    // ---- stage Q (32x64) -> smem tf32, then to regs ----
#pragma unroll
    for (int i = 0; i < 2; i++) {
        const int idx4 = t + 256 * i;                 // 512 float4s
        const int row = idx4 >> 4, c = (idx4 & 15) * 4;
        float4 qv = *(const float4*)(Q + (size_t)row * DKH + c);
        *(uint4*)&Qs[row * QSTR + c] = make_uint4(f2tf(qv.x), f2tf(qv.y), f2tf(qv.z), f2tf(qv.w));
    }
    __syncthreads();

    unsigned qr[8][4];
#pragma unroll
    for (int ks = 0; ks < 8; ks++) {
        const int kk = ks * 8;
        qr[ks][0] = Qs[r0 * QSTR + kk + tg];
        qr[ks][1] = Qs[(r0 + 8) * QSTR + kk + tg];
        qr[ks][2] = Qs[r0 * QSTR + kk + tg + 4];
        qr[ks][3] = Qs[(r0 + 8) * QSTR + kk + tg + 4];
    }
    __syncthreads();   // Q frags fully in registers before any buffer reuse

    float rs0 = 0.f, rs1 = 0.f;

    // ---- Phase 1: S tiles, exp -> P, row sums ----
    for (int kt = 0; kt < 8; kt++) {
        unsigned* Kb = Ks + (kt & 1) * (128 * KSTR);
#pragma unroll
        for (int i = 0; i < 8; i++) {
            const int idx4 = t + 256 * i;             // 2048 float4s
            const int row = idx4 >> 4, c = (idx4 & 15) * 4;
            float4 kv = *(const float4*)(Kp + (size_t)(kt * 128 + row) * DKH + c);
            *(uint4*)&Kb[row * KSTR + c] = make_uint4(f2tf(kv.x), f2tf(kv.y), f2tf(kv.z), f2tf(kv.w));
        }
        __syncthreads();

        float s[4][4];
#pragma unroll
        for (int nt = 0; nt < 4; nt++)
#pragma unroll
            for (int i = 0; i < 4; i++) s[nt][i] = 0.f;

#pragma unroll
        for (int ks = 0; ks < 8; ks++) {
            const int kk = ks * 8;
            unsigned bf[4][2];
#pragma unroll
            for (int nt = 0; nt < 4; nt++) {
                const int ncol = wn * 32 + nt * 8 + g;
                bf[nt][0] = Kb[ncol * KSTR + kk + tg];
                bf[nt][1] = Kb[ncol * KSTR + kk + tg + 4];
            }
#pragma unroll
            for (int nt = 0; nt < 4; nt++)
                mma8(s[nt][0], s[nt][1], s[nt][2], s[nt][3],
                     qr[ks][0], qr[ks][1], qr[ks][2], qr[ks][3],
                     bf[nt][0], bf[nt][1]);
        }

        // epilogue: gate * 0.125, mask, exp -> P; accumulate row sums
#pragma unroll
        for (int nt = 0; nt < 4; nt++) {
            const int col = kt * 128 + wn * 32 + nt * 8 + 2 * tg;
            const size_t gbase0 = (size_t)z * LS * LS + (size_t)(rowBase + r0) * LS + col;
            const size_t mbase0 = (size_t)b * LS * LS + (size_t)(rowBase + r0) * LS + col;
            {
                float2 gv = *(const float2*)&gate[gbase0];
                int2   mv = *(const int2*)&mask[mbase0];
                float e0 = (mv.x > 0) ? 0.f : __expf(s[nt][0] * 0.125f * gv.x);
                float e1 = (mv.y > 0) ? 0.f : __expf(s[nt][1] * 0.125f * gv.y);
                *(float2*)&P[r0 * PSTR + col] = make_float2(e0, e1);
                rs0 += e0 + e1;
            }
            {
                float2 gv = *(const float2*)&gate[gbase0 + 8 * LS];
                int2   mv = *(const int2*)&mask[mbase0 + 8 * LS];
                float e2 = (mv.x > 0) ? 0.f : __expf(s[nt][2] * 0.125f * gv.x);
                float e3 = (mv.y > 0) ? 0.f : __expf(s[nt][3] * 0.125f * gv.y);
                *(float2*)&P[(r0 + 8) * PSTR + col] = make_float2(e2, e3);
                rs1 += e2 + e3;
            }
        }
    }

    // ---- row-sum reduction -> invs ----
    {
        float v0 = rs0, v1 = rs1;
        v0 += __shfl_xor_sync(0xffffffffu, v0, 1);
        v0 += __shfl_xor_sync(0xffffffffu, v0, 2);
        v1 += __shfl_xor_sync(0xffffffffu, v1, 1);
        v1 += __shfl_xor_sync(0xffffffffu, v1, 2);
        if (tg == 0) {
            red[wn * FROWS + r0]     = v0;
            red[wn * FROWS + r0 + 8] = v1;
        }
    }
    __syncthreads();
    if (t < FROWS)
        invs[t] = 1.f / (red[t] + red[FROWS + t] + red[2 * FROWS + t] + red[3 * FROWS + t]);
    __syncthreads();

    // ---- Phase 2: write normalized attn once (coalesced) ----
#pragma unroll
    for (int j = 0; j < 32; j++) {
        const int f4 = t + 256 * j;                   // 8192 float4s
        const int row = f4 >> 8, c4 = (f4 & 255) * 4;
        float4 pv = *(float4*)&P[row * PSTR + c4];
        const float iv = invs[row];
        pv.x *= iv; pv.y *= iv; pv.z *= iv; pv.w *= iv;
        *(float4*)&attn[(size_t)z * LS * LS + (size_t)(rowBase + row) * LS + c4] = pv;
    }

    // ---- Phase 3: O = P @ V (unnormalized), scale at end ----
    float o[2][4];
#pragma unroll
    for (int nf = 0; nf < 2; nf++)
#pragma unroll
        for (int i = 0; i < 4; i++) o[nf][i] = 0.f;

    for (int kt = 0; kt < 8; kt++) {
        unsigned* Vb = Ks + (kt & 1) * (128 * KSTR);
#pragma unroll
        for (int i = 0; i < 8; i++) {
            const int idx4 = t + 256 * i;
            const int row = idx4 >> 4, c = (idx4 & 15) * 4;
            float4 vv = *(const float4*)(V + (size_t)(kt * 128 + row) * DVH + c);
            *(uint4*)&Vb[row * KSTR + c] = make_uint4(f2tf(vv.x), f2tf(vv.y), f2tf(vv.z), f2tf(vv.w));
        }
        __syncthreads();

#pragma unroll
        for (int ks = 0; ks < 16; ks++) {
            const int kk = kt * 128 + ks * 8;
            const int kl = ks * 8;
            unsigned a0 = f2tf(P[r0 * PSTR + kk + tg]);
            unsigned a1 = f2tf(P[(r0 + 8) * PSTR + kk + tg]);
            unsigned a2 = f2tf(P[r0 * PSTR + kk + tg + 4]);
            unsigned a3 = f2tf(P[(r0 + 8) * PSTR + kk + tg + 4]);
#pragma unroll
            for (int nf = 0; nf < 2; nf++) {
                const int col = wn * 16 + nf * 8 + g;
                unsigned b0 = Vb[(kl + tg) * KSTR + col];
                unsigned b1 = Vb[(kl + tg + 4) * KSTR + col];
                mma8(o[nf][0], o[nf][1], o[nf][2], o[nf][3], a0, a1, a2, a3, b0, b1);
            }
        }
        __syncthreads();
    }

    const float iv0 = invs[r0], iv1 = invs[r0 + 8];
#pragma unroll
    for (int nf = 0; nf < 2; nf++) {
        const int col = h * 64 + wn * 16 + nf * 8 + 2 * tg;
        const size_t dst0 = ((size_t)(b * LS + rowBase + r0)) * DMOD + col;
        *(float2*)&ctx[dst0]             = make_float2(o[nf][0] * iv0, o[nf][1] * iv0);
        *(float2*)&ctx[dst0 + 8 * DMOD]  = make_float2(o[nf][2] * iv1, o[nf][3] * iv1);
    }
}

// ---------------------------------------------------------------------------
// Residual + LayerNorm.  grid 4096, block 256.
// ---------------------------------------------------------------------------
__global__ void ln_kernel(const float* __restrict__ resid,
                          const float* __restrict__ gamma,
                          const float* __restrict__ beta,
                          const float* __restrict__ fcv,
                          float* __restrict__ out)
{
    __shared__ float red[256];
    const int r = blockIdx.x;
    const float* xf = fcv + (size_t)r * DMOD;
    const float* rz = resid + (size_t)r * DMOD;
    const int t = threadIdx.x;

    float v[4];
    float sum = 0.f;
#pragma unroll
    for (int j = 0; j < 4; j++) {
        v[j] = xf[t + 256 * j] + rz[t + 256 * j];
        sum += v[j];
    }
    red[t] = sum; __syncthreads();
    for (int s = 128; s > 0; s >>= 1) {
        if (t < s) red[t] += red[t + s];
        __syncthreads();
    }
    const float mu = red[0] * (1.f / DMOD);
    __syncthreads();

    float vs = 0.f;
#pragma unroll
    for (int j = 0; j < 4; j++) {
        const float d = v[j] - mu;
        vs += d * d;
    }
    red[t] = vs; __syncthreads();
    for (int s = 128; s > 0; s >>= 1) {
        if (t < s) red[t] += red[t + s];
        __syncthreads();
    }
    const float var = red[0] * (1.f / DMOD);
    const float inv = rsqrtf(var + 1e-5f);
#pragma unroll
    for (int j = 0; j < 4; j++) {
        const int cc = t + 256 * j;
        out[(size_t)r * DMOD + cc] = (v[j] - mu) * inv * gamma[cc] + beta[cc];
    }
}

// ---------------------------------------------------------------------------
extern "C" void kernel_launch(void* const* d_in, const int* in_sizes, int n_in,
                              void* d_out, int out_size)
{
    const float* q    = (const float*)d_in[0];
    const float* k    = (const float*)d_in[1];
    const float* v    = (const float*)d_in[2];
    const int*   mask = (const int*)  d_in[3];
    const float* gate = (const float*)d_in[4];
    const float* w_q  = (const float*)d_in[5];
    const float* b_q  = (const float*)d_in[6];
    const float* w_k  = (const float*)d_in[7];
    const float* b_k  = (const float*)d_in[8];
    const float* w_v  = (const float*)d_in[9];
    const float* b_v  = (const float*)d_in[10];
    const float* w_fc = (const float*)d_in[11];
    const float* b_fc = (const float*)d_in[12];
    const float* ln_g = (const float*)d_in[13];
    const float* ln_b = (const float*)d_in[14];
    float* out = (float*)d_out;

    float *p_qh, *p_kh, *p_vh, *p_ctx, *p_fc, *p_attn_s, *p_outs;
    cudaGetSymbolAddress((void**)&p_qh,     g_qh);
    cudaGetSymbolAddress((void**)&p_kh,     g_kh);
    cudaGetSymbolAddress((void**)&p_vh,     g_vh);
    cudaGetSymbolAddress((void**)&p_ctx,    g_ctx);
    cudaGetSymbolAddress((void**)&p_fc,     g_fc);
    cudaGetSymbolAddress((void**)&p_attn_s, g_attn);
    cudaGetSymbolAddress((void**)&p_outs,   g_outs);

    // Reference returns (out, attn).  Resolve destinations from out_size.
    float* attn_ptr;
    float* out_ptr;
    const long long osz = (long long)out_size;
    if (osz >= OUT_ELEMS + ATT_ELEMS) {        // concatenated tuple
        out_ptr  = out;
        attn_ptr = out + OUT_ELEMS;
    } else if (osz >= ATT_ELEMS) {             // attn only
        out_ptr  = p_outs;
        attn_ptr = out;
    } else {                                   // out only
        out_ptr  = out;
        attn_ptr = p_attn_s;
    }

    // Opt in to >48KB dynamic smem for the fused kernel (idempotent).
    cudaFuncSetAttribute(fused_attn, cudaFuncAttributeMaxDynamicSharedMemorySize,
                         FUSED_SMEM_BYTES);

    // 1) QKV projections (tf32 tensor cores)
    gemm_tf32<<<dim3(8, 32), 256>>>(q, w_q, b_q, p_qh, DMOD, NH * DKH, DKH);
    gemm_tf32<<<dim3(8, 32), 256>>>(k, w_k, b_k, p_kh, DMOD, NH * DKH, DKH);
    gemm_tf32<<<dim3(8, 32), 256>>>(v, w_v, b_v, p_vh, DMOD, NH * DVH, DVH);

    // 2) Fused scores + gate/mask + exp + softmax + attn write + AV
    fused_attn<<<dim3(LS / FROWS, ZH), 256, FUSED_SMEM_BYTES>>>(
        p_qh, p_kh, p_vh, gate, mask, attn_ptr, p_ctx);

    // 3) FC projection
    gemm_tf32<<<dim3(8, 32), 256>>>(p_ctx, w_fc, b_fc, p_fc, DMOD, DMOD, DMOD);

    // 4) Residual + LayerNorm -> final out
    ln_kernel<<<4096, 256>>>(q, ln_g, ln_b, p_fc, out_ptr);
}

// round 5
// speedup vs baseline: 1.2143x; 1.2143x over previous
#include <cuda_runtime.h>
#include <math.h>

// Problem constants
#define BB 4
#define LS 1024
#define DMOD 1024
#define NH 16
#define DKH 64
#define DVH 64
#define ZH (BB * NH)

#define OUT_ELEMS ((long long)BB * LS * DMOD)            // 4194304
#define ATT_ELEMS ((long long)ZH * LS * LS)              // 67108864

// -------------------- scratch (device globals; no allocation allowed) ------
__device__ float g_qh[ZH * LS * DKH];        // [B,H,L,DK]
__device__ float g_kh[ZH * LS * DKH];
__device__ float g_vh[ZH * LS * DVH];
__device__ float g_ctx[BB * LS * NH * DVH];  // [B,L,H*DV]
__device__ float g_fc[BB * LS * DMOD];       // pre-LN fc output
__device__ float g_part[(size_t)ZH * LS * 16]; // per-(z,row) partial exp sums, 16 col tiles
__device__ float g_invsum[ZH * LS];          // 1 / rowsum
__device__ float g_attn[(size_t)ZH * LS * LS]; // attn scratch (fallback)
__device__ float g_outs[BB * LS * DMOD];     // fallback out sink

// ---------------------------------------------------------------------------
// helpers
// ---------------------------------------------------------------------------
__device__ __forceinline__ unsigned f2tf(float f) {
    unsigned r;
    asm("cvt.rna.tf32.f32 %0, %1;" : "=r"(r) : "f"(f));
    return r;
}

__device__ __forceinline__ void mma8(float& c0, float& c1, float& c2, float& c3,
                                     unsigned a0, unsigned a1, unsigned a2, unsigned a3,
                                     unsigned b0, unsigned b1) {
    asm volatile(
        "mma.sync.aligned.m16n8k8.row.col.f32.tf32.tf32.f32 "
        "{%0,%1,%2,%3}, {%4,%5,%6,%7}, {%8,%9}, {%0,%1,%2,%3};\n"
        : "+f"(c0), "+f"(c1), "+f"(c2), "+f"(c3)
        : "r"(a0), "r"(a1), "r"(a2), "r"(a3), "r"(b0), "r"(b1));
}

__device__ __forceinline__ void cpa16(void* s, const void* g) {
    asm volatile("cp.async.cg.shared.global [%0], [%1], 16;\n"
        :: "r"((unsigned)__cvta_generic_to_shared(s)), "l"(g) : "memory");
}
__device__ __forceinline__ void cpa_commit() {
    asm volatile("cp.async.commit_group;\n" ::: "memory");
}
template <int N> __device__ __forceinline__ void cpa_wait() {
    asm volatile("cp.async.wait_group %0;\n" :: "n"(N) : "memory");
}

// ---------------------------------------------------------------------------
// TF32 NT GEMM + bias, cp.async double-buffered.
// C[r,n] = sum_k A[r,k] * W[n,k] + bias[n]; A [M,K], W [N,K] row-major.
// Tile 128(m) x 64(n), BK=32, 256 threads (8 warps, 4m x 2n, warp 32x32).
// Output in [B,H,L,Dhead] layout (Dhead==N -> plain row-major).
// Dynamic smem: 2*(128*36 + 64*36)*4 = 55296 B.  2 CTAs/SM.
// ---------------------------------------------------------------------------
#define GEMM_SMEM_BYTES ((2 * 128 * 36 + 2 * 64 * 36) * 4)

__global__ void __launch_bounds__(256, 2)
gemm_v2(const float* __restrict__ A, const float* __restrict__ W,
        const float* __restrict__ bias, float* __restrict__ out,
        int K, int N, int Dhead)
{
    extern __shared__ float gsm[];
    float* As = gsm;                 // 2 x (128 x 36)
    float* Ws = gsm + 2 * 128 * 36;  // 2 x (64 x 36)

    const int t = threadIdx.x, lane = t & 31, w = t >> 5;
    const int wm = w >> 1, wn = w & 1;     // 4m x 2n warps, warp tile 32x32
    const int g = lane >> 2, tg = lane & 3;
    const int rowBase = blockIdx.y * 128;
    const int colBase = blockIdx.x * 64;

    const float* Ab = A + (size_t)rowBase * K;
    const float* Wb = W + (size_t)colBase * K;

    float c[2][4][4];
#pragma unroll
    for (int mt = 0; mt < 2; mt++)
#pragma unroll
        for (int nt = 0; nt < 4; nt++)
#pragma unroll
            for (int i = 0; i < 4; i++) c[mt][nt][i] = 0.f;

    const int nk = K >> 5;

    // prologue: stage tile 0
    {
        float* Ad = As;
        float* Wd = Ws;
#pragma unroll
        for (int i = 0; i < 4; i++) {
            const int idx4 = t + 256 * i;
            const int row = idx4 >> 3, c4 = (idx4 & 7) * 4;
            cpa16(&Ad[row * 36 + c4], Ab + (size_t)row * K + c4);
        }
#pragma unroll
        for (int i = 0; i < 2; i++) {
            const int idx4 = t + 256 * i;
            const int row = idx4 >> 3, c4 = (idx4 & 7) * 4;
            cpa16(&Wd[row * 36 + c4], Wb + (size_t)row * K + c4);
        }
        cpa_commit();
    }

    for (int kt = 0; kt < nk; kt++) {
        if (kt + 1 < nk) {
            float* Ad = As + ((kt + 1) & 1) * (128 * 36);
            float* Wd = Ws + ((kt + 1) & 1) * (64 * 36);
            const int ko = (kt + 1) * 32;
#pragma unroll
            for (int i = 0; i < 4; i++) {
                const int idx4 = t + 256 * i;
                const int row = idx4 >> 3, c4 = (idx4 & 7) * 4;
                cpa16(&Ad[row * 36 + c4], Ab + (size_t)row * K + ko + c4);
            }
#pragma unroll
            for (int i = 0; i < 2; i++) {
                const int idx4 = t + 256 * i;
                const int row = idx4 >> 3, c4 = (idx4 & 7) * 4;
                cpa16(&Wd[row * 36 + c4], Wb + (size_t)row * K + ko + c4);
            }
            cpa_commit();
            cpa_wait<1>();
        } else {
            cpa_wait<0>();
        }
        __syncthreads();

        const float* Ac = As + (kt & 1) * (128 * 36);
        const float* Wc = Ws + (kt & 1) * (64 * 36);
#pragma unroll
        for (int ks = 0; ks < 4; ks++) {
            const int kk = ks * 8;
            unsigned a[2][4], bf[4][2];
#pragma unroll
            for (int mt = 0; mt < 2; mt++) {
                const int r = (wm * 32 + mt * 16 + g) * 36 + kk + tg;
                a[mt][0] = f2tf(Ac[r]);
                a[mt][1] = f2tf(Ac[r + 8 * 36]);
                a[mt][2] = f2tf(Ac[r + 4]);
                a[mt][3] = f2tf(Ac[r + 8 * 36 + 4]);
            }
#pragma unroll
            for (int nt = 0; nt < 4; nt++) {
                const int r = (wn * 32 + nt * 8 + g) * 36 + kk + tg;
                bf[nt][0] = f2tf(Wc[r]);
                bf[nt][1] = f2tf(Wc[r + 4]);
            }
#pragma unroll
            for (int mt = 0; mt < 2; mt++)
#pragma unroll
                for (int nt = 0; nt < 4; nt++)
                    mma8(c[mt][nt][0], c[mt][nt][1], c[mt][nt][2], c[mt][nt][3],
                         a[mt][0], a[mt][1], a[mt][2], a[mt][3],
                         bf[nt][0], bf[nt][1]);
        }
        __syncthreads();
    }

    const int H = N / Dhead;
#pragma unroll
    for (int mt = 0; mt < 2; mt++) {
        const int rr = rowBase + wm * 32 + mt * 16 + g;
        const int b_ = rr >> 10, l = rr & 1023;
#pragma unroll
        for (int nt = 0; nt < 4; nt++) {
            const int cc = colBase + wn * 32 + nt * 8 + 2 * tg;
            const int h = cc / Dhead, d = cc % Dhead;
            const size_t dst = (((size_t)(b_ * H + h)) * LS + l) * Dhead + d;
            const float b0 = bias[cc], b1 = bias[cc + 1];
            *(float2*)&out[dst]             = make_float2(c[mt][nt][0] + b0, c[mt][nt][1] + b1);
            *(float2*)&out[dst + 8 * Dhead] = make_float2(c[mt][nt][2] + b0, c[mt][nt][3] + b1);
        }
    }
}

// ---------------------------------------------------------------------------
// Scores: tile 128(q) x 64(k), whole DK=64 staged once via cp.async.
// S = (Q K^T) * 0.125 * gate; masked -> 0; attn <- exp(S) (UNNORMALIZED);
// part[(z*LS+row)*16 + kTile] = partial row sum.
// 256 threads (8 warps, 4m x 2n, warp 32x32).  grid (16, 8, 64).
// Dynamic smem: (128*68 + 64*68)*4 + 2*128*4 = 53248 B.  2 CTAs/SM.
// ---------------------------------------------------------------------------
#define SC_SMEM_BYTES (((128 + 64) * 68) * 4 + 2 * 128 * 4)

__global__ void __launch_bounds__(256, 2)
scores_v2(const float* __restrict__ qh, const float* __restrict__ kh,
          const float* __restrict__ gate, const int* __restrict__ mask,
          float* __restrict__ attn, float* __restrict__ part)
{
    extern __shared__ float ssm[];
    float* Qs    = ssm;                    // 128 x 68
    float* Ksm   = ssm + 128 * 68;         // 64 x 68
    float* redsh = ssm + (128 + 64) * 68;  // 2 x 128

    const int t = threadIdx.x, lane = t & 31, w = t >> 5;
    const int wm = w >> 1, wn = w & 1;
    const int g = lane >> 2, tg = lane & 3;
    const int z = blockIdx.z, b = z >> 4;
    const int qBase = blockIdx.y * 128;
    const int kBase = blockIdx.x * 64;

    const float* Q  = qh + (size_t)z * LS * DKH + (size_t)qBase * DKH;
    const float* Kp = kh + (size_t)z * LS * DKH + (size_t)kBase * DKH;

    // stage Q (128x64) and K (64x64)
#pragma unroll
    for (int i = 0; i < 8; i++) {
        const int idx4 = t + 256 * i;
        const int row = idx4 >> 4, c = (idx4 & 15) * 4;
        cpa16(&Qs[row * 68 + c], Q + (size_t)row * DKH + c);
    }
#pragma unroll
    for (int i = 0; i < 4; i++) {
        const int idx4 = t + 256 * i;
        const int row = idx4 >> 4, c = (idx4 & 15) * 4;
        cpa16(&Ksm[row * 68 + c], Kp + (size_t)row * DKH + c);
    }
    cpa_commit();
    cpa_wait<0>();
    __syncthreads();

    float s[2][4][4];
#pragma unroll
    for (int mt = 0; mt < 2; mt++)
#pragma unroll
        for (int nt = 0; nt < 4; nt++)
#pragma unroll
            for (int i = 0; i < 4; i++) s[mt][nt][i] = 0.f;

#pragma unroll
    for (int ks = 0; ks < 8; ks++) {
        const int kk = ks * 8;
        unsigned a[2][4], bf[4][2];
#pragma unroll
        for (int mt = 0; mt < 2; mt++) {
            const int r = (wm * 32 + mt * 16 + g) * 68 + kk + tg;
            a[mt][0] = f2tf(Qs[r]);
            a[mt][1] = f2tf(Qs[r + 8 * 68]);
            a[mt][2] = f2tf(Qs[r + 4]);
            a[mt][3] = f2tf(Qs[r + 8 * 68 + 4]);
        }
#pragma unroll
        for (int nt = 0; nt < 4; nt++) {
            const int r = (wn * 32 + nt * 8 + g) * 68 + kk + tg;
            bf[nt][0] = f2tf(Ksm[r]);
            bf[nt][1] = f2tf(Ksm[r + 4]);
        }
#pragma unroll
        for (int mt = 0; mt < 2; mt++)
#pragma unroll
            for (int nt = 0; nt < 4; nt++)
                mma8(s[mt][nt][0], s[mt][nt][1], s[mt][nt][2], s[mt][nt][3],
                     a[mt][0], a[mt][1], a[mt][2], a[mt][3],
                     bf[nt][0], bf[nt][1]);
    }

    // epilogue: gate*0.125, mask, exp -> attn; row-sum partials
    float rs[2][2];
    rs[0][0] = rs[0][1] = rs[1][0] = rs[1][1] = 0.f;

#pragma unroll
    for (int mt = 0; mt < 2; mt++) {
        const int rr = qBase + wm * 32 + mt * 16 + g;
#pragma unroll
        for (int nt = 0; nt < 4; nt++) {
            const int cc = kBase + wn * 32 + nt * 8 + 2 * tg;
            const size_t base  = (size_t)z * LS * LS + (size_t)rr * LS + cc;
            const size_t mbase = (size_t)b * LS * LS + (size_t)rr * LS + cc;
            {
                float2 gv = *(const float2*)&gate[base];
                int2   mv = *(const int2*)&mask[mbase];
                float e0 = (mv.x > 0) ? 0.f : __expf(s[mt][nt][0] * 0.125f * gv.x);
                float e1 = (mv.y > 0) ? 0.f : __expf(s[mt][nt][1] * 0.125f * gv.y);
                *(float2*)&attn[base] = make_float2(e0, e1);
                rs[mt][0] += e0 + e1;
            }
            {
                float2 gv = *(const float2*)&gate[base + 8 * LS];
                int2   mv = *(const int2*)&mask[mbase + 8 * LS];
                float e2 = (mv.x > 0) ? 0.f : __expf(s[mt][nt][2] * 0.125f * gv.x);
                float e3 = (mv.y > 0) ? 0.f : __expf(s[mt][nt][3] * 0.125f * gv.y);
                *(float2*)&attn[base + 8 * LS] = make_float2(e2, e3);
                rs[mt][1] += e2 + e3;
            }
        }
    }

#pragma unroll
    for (int mt = 0; mt < 2; mt++)
#pragma unroll
        for (int hf = 0; hf < 2; hf++) {
            float v = rs[mt][hf];
            v += __shfl_xor_sync(0xffffffffu, v, 1);
            v += __shfl_xor_sync(0xffffffffu, v, 2);
            rs[mt][hf] = v;
        }
    if (tg == 0) {
#pragma unroll
        for (int mt = 0; mt < 2; mt++) {
            redsh[wn * 128 + wm * 32 + mt * 16 + g]     = rs[mt][0];
            redsh[wn * 128 + wm * 32 + mt * 16 + g + 8] = rs[mt][1];
        }
    }
    __syncthreads();
    if (t < 128)
        part[((size_t)z * LS + qBase + t) * 16 + blockIdx.x] = redsh[t] + redsh[128 + t];
}

// ---------------------------------------------------------------------------
// Reduce 16 partials -> 1/rowsum.  grid 256, block 256.
// ---------------------------------------------------------------------------
__global__ void reduce_inv(const float* __restrict__ part, float* __restrict__ invsum)
{
    const int i = blockIdx.x * 256 + threadIdx.x;   // 65536 rows
    float s = 0.f;
#pragma unroll
    for (int j = 0; j < 16; j++) s += part[(size_t)i * 16 + j];
    invsum[i] = 1.f / s;
}

// ---------------------------------------------------------------------------
// AV: tile 64(q) x 64(d), BK=32, software-pipelined.
// Reads unnormalized attn, normalizes (writes attn back normalized, once),
// MMAs normalized P against V (cp.async).  ctx needs no rescale.
// 256 threads (8 warps, 2m x 4n, warp 32x16).  grid (16, 64).
// Static smem ~37.5 KB; launch_bounds(256,3).
// ---------------------------------------------------------------------------
__global__ void __launch_bounds__(256, 3)
av_v2(float* __restrict__ attn, const float* __restrict__ invsum,
      const float* __restrict__ vh, float* __restrict__ ctx)
{
    __shared__ float Ps[2][64 * 36];
    __shared__ float Vs[2][32 * 72];
    __shared__ float invsh[64];

    const int t = threadIdx.x, lane = t & 31, w = t >> 5;
    const int wm = w >> 2, wn = w & 3;     // 2m x 4n warps, warp tile 32x16
    const int g = lane >> 2, tg = lane & 3;
    const int z = blockIdx.y, b = z >> 4, h = z & 15;
    const int rowBase = blockIdx.x * 64;

    float* P = attn + (size_t)z * LS * LS + (size_t)rowBase * LS;
    const float* V = vh + (size_t)z * LS * DVH;

    if (t < 64) invsh[t] = invsum[z * LS + rowBase + t];
    __syncthreads();

    // P loader mapping: 2 float4 per thread per tile
    const int p_row0 = t >> 3,          p_c0 = (t & 7) * 4;
    const int p_row1 = (t + 256) >> 3,  p_c1 = ((t + 256) & 7) * 4;
    // V loader mapping
    const int v_row0 = t >> 4,          v_c0 = (t & 15) * 4;
    const int v_row1 = (t + 256) >> 4,  v_c1 = ((t + 256) & 15) * 4;

    float c[2][2][4];
#pragma unroll
    for (int mt = 0; mt < 2; mt++)
#pragma unroll
        for (int nt = 0; nt < 2; nt++)
#pragma unroll
            for (int i = 0; i < 4; i++) c[mt][nt][i] = 0.f;

    // prologue: V(0) async, P(0) -> regs
    cpa16(&Vs[0][v_row0 * 72 + v_c0], V + (size_t)v_row0 * DVH + v_c0);
    cpa16(&Vs[0][v_row1 * 72 + v_c1], V + (size_t)v_row1 * DVH + v_c1);
    cpa_commit();
    float4 pv0 = *(const float4*)(P + (size_t)p_row0 * LS + p_c0);
    float4 pv1 = *(const float4*)(P + (size_t)p_row1 * LS + p_c1);

    for (int kt = 0; kt < 32; kt++) {
        float4 nv0 = make_float4(0.f, 0.f, 0.f, 0.f);
        float4 nv1 = make_float4(0.f, 0.f, 0.f, 0.f);
        if (kt + 1 < 32) {
            const int ko = (kt + 1) * 32;
            cpa16(&Vs[(kt + 1) & 1][v_row0 * 72 + v_c0], V + (size_t)(ko + v_row0) * DVH + v_c0);
            cpa16(&Vs[(kt + 1) & 1][v_row1 * 72 + v_c1], V + (size_t)(ko + v_row1) * DVH + v_c1);
            cpa_commit();
            nv0 = *(const float4*)(P + (size_t)p_row0 * LS + ko + p_c0);
            nv1 = *(const float4*)(P + (size_t)p_row1 * LS + ko + p_c1);
        }

        // normalize current P, write attn back, stage to smem
        {
            const int ko = kt * 32;
            const float i0 = invsh[p_row0];
            pv0.x *= i0; pv0.y *= i0; pv0.z *= i0; pv0.w *= i0;
            *(float4*)(P + (size_t)p_row0 * LS + ko + p_c0) = pv0;
            *(float4*)&Ps[kt & 1][p_row0 * 36 + p_c0] = pv0;
            const float i1 = invsh[p_row1];
            pv1.x *= i1; pv1.y *= i1; pv1.z *= i1; pv1.w *= i1;
            *(float4*)(P + (size_t)p_row1 * LS + ko + p_c1) = pv1;
            *(float4*)&Ps[kt & 1][p_row1 * 36 + p_c1] = pv1;
        }

        if (kt + 1 < 32) cpa_wait<1>(); else cpa_wait<0>();
        __syncthreads();

        const float* Pc = Ps[kt & 1];
        const float* Vc = Vs[kt & 1];
#pragma unroll
        for (int ks = 0; ks < 4; ks++) {
            const int kk = ks * 8;
            unsigned a[2][4], bf[2][2];
#pragma unroll
            for (int mt = 0; mt < 2; mt++) {
                const int r = (wm * 32 + mt * 16 + g) * 36 + kk + tg;
                a[mt][0] = f2tf(Pc[r]);
                a[mt][1] = f2tf(Pc[r + 8 * 36]);
                a[mt][2] = f2tf(Pc[r + 4]);
                a[mt][3] = f2tf(Pc[r + 8 * 36 + 4]);
            }
#pragma unroll
            for (int nt = 0; nt < 2; nt++) {
                const int col = wn * 16 + nt * 8 + g;
                bf[nt][0] = f2tf(Vc[(kk + tg) * 72 + col]);
                bf[nt][1] = f2tf(Vc[(kk + tg + 4) * 72 + col]);
            }
#pragma unroll
            for (int mt = 0; mt < 2; mt++)
#pragma unroll
                for (int nt = 0; nt < 2; nt++)
                    mma8(c[mt][nt][0], c[mt][nt][1], c[mt][nt][2], c[mt][nt][3],
                         a[mt][0], a[mt][1], a[mt][2], a[mt][3],
                         bf[nt][0], bf[nt][1]);
        }
        __syncthreads();
        pv0 = nv0;
        pv1 = nv1;
    }

#pragma unroll
    for (int mt = 0; mt < 2; mt++) {
        const int rr = rowBase + wm * 32 + mt * 16 + g;
#pragma unroll
        for (int nt = 0; nt < 2; nt++) {
            const int d = wn * 16 + nt * 8 + 2 * tg;
            const size_t dst = ((size_t)(b * LS + rr)) * DMOD + h * 64 + d;
            *(float2*)&ctx[dst]            = make_float2(c[mt][nt][0], c[mt][nt][1]);
            *(float2*)&ctx[dst + 8 * DMOD] = make_float2(c[mt][nt][2], c[mt][nt][3]);
        }
    }
}

// ---------------------------------------------------------------------------
// Residual + LayerNorm.  grid 4096, block 256.
// ---------------------------------------------------------------------------
__global__ void ln_kernel(const float* __restrict__ resid,
                          const float* __restrict__ gamma,
                          const float* __restrict__ beta,
                          const float* __restrict__ fcv,
                          float* __restrict__ out)
{
    __shared__ float red[256];
    const int r = blockIdx.x;
    const float* xf = fcv + (size_t)r * DMOD;
    const float* rz = resid + (size_t)r * DMOD;
    const int t = threadIdx.x;

    float v[4];
    float sum = 0.f;
#pragma unroll
    for (int j = 0; j < 4; j++) {
        v[j] = xf[t + 256 * j] + rz[t + 256 * j];
        sum += v[j];
    }
    red[t] = sum; __syncthreads();
    for (int s = 128; s > 0; s >>= 1) {
        if (t < s) red[t] += red[t + s];
        __syncthreads();
    }
    const float mu = red[0] * (1.f / DMOD);
    __syncthreads();

    float vs = 0.f;
#pragma unroll
    for (int j = 0; j < 4; j++) {
        const float d = v[j] - mu;
        vs += d * d;
    }
    red[t] = vs; __syncthreads();
    for (int s = 128; s > 0; s >>= 1) {
        if (t < s) red[t] += red[t + s];
        __syncthreads();
    }
    const float var = red[0] * (1.f / DMOD);
    const float inv = rsqrtf(var + 1e-5f);
#pragma unroll
    for (int j = 0; j < 4; j++) {
        const int cc = t + 256 * j;
        out[(size_t)r * DMOD + cc] = (v[j] - mu) * inv * gamma[cc] + beta[cc];
    }
}

// ---------------------------------------------------------------------------
extern "C" void kernel_launch(void* const* d_in, const int* in_sizes, int n_in,
                              void* d_out, int out_size)
{
    const float* q    = (const float*)d_in[0];
    const float* k    = (const float*)d_in[1];
    const float* v    = (const float*)d_in[2];
    const int*   mask = (const int*)  d_in[3];
    const float* gate = (const float*)d_in[4];
    const float* w_q  = (const float*)d_in[5];
    const float* b_q  = (const float*)d_in[6];
    const float* w_k  = (const float*)d_in[7];
    const float* b_k  = (const float*)d_in[8];
    const float* w_v  = (const float*)d_in[9];
    const float* b_v  = (const float*)d_in[10];
    const float* w_fc = (const float*)d_in[11];
    const float* b_fc = (const float*)d_in[12];
    const float* ln_g = (const float*)d_in[13];
    const float* ln_b = (const float*)d_in[14];
    float* out = (float*)d_out;

    float *p_qh, *p_kh, *p_vh, *p_ctx, *p_fc, *p_part, *p_inv, *p_attn_s, *p_outs;
    cudaGetSymbolAddress((void**)&p_qh,     g_qh);
    cudaGetSymbolAddress((void**)&p_kh,     g_kh);
    cudaGetSymbolAddress((void**)&p_vh,     g_vh);
    cudaGetSymbolAddress((void**)&p_ctx,    g_ctx);
    cudaGetSymbolAddress((void**)&p_fc,     g_fc);
    cudaGetSymbolAddress((void**)&p_part,   g_part);
    cudaGetSymbolAddress((void**)&p_inv,    g_invsum);
    cudaGetSymbolAddress((void**)&p_attn_s, g_attn);
    cudaGetSymbolAddress((void**)&p_outs,   g_outs);

    // Reference returns (out, attn).  Resolve destinations from out_size.
    float* attn_ptr;
    float* out_ptr;
    const long long osz = (long long)out_size;
    if (osz >= OUT_ELEMS + ATT_ELEMS) {        // concatenated tuple
        out_ptr  = out;
        attn_ptr = out + OUT_ELEMS;
    } else if (osz >= ATT_ELEMS) {             // attn only
        out_ptr  = p_outs;
        attn_ptr = out;
    } else {                                   // out only
        out_ptr  = out;
        attn_ptr = p_attn_s;
    }

    // opt in to >48KB dynamic smem (idempotent)
    cudaFuncSetAttribute(gemm_v2, cudaFuncAttributeMaxDynamicSharedMemorySize,
                         GEMM_SMEM_BYTES);
    cudaFuncSetAttribute(scores_v2, cudaFuncAttributeMaxDynamicSharedMemorySize,
                         SC_SMEM_BYTES);

    // 1) QKV projections
    gemm_v2<<<dim3(16, 32), 256, GEMM_SMEM_BYTES>>>(q, w_q, b_q, p_qh, DMOD, NH * DKH, DKH);
    gemm_v2<<<dim3(16, 32), 256, GEMM_SMEM_BYTES>>>(k, w_k, b_k, p_kh, DMOD, NH * DKH, DKH);
    gemm_v2<<<dim3(16, 32), 256, GEMM_SMEM_BYTES>>>(v, w_v, b_v, p_vh, DMOD, NH * DVH, DVH);

    // 2) Scores + gate/mask + exp + partial row sums (unnormalized attn)
    scores_v2<<<dim3(16, 8, ZH), 256, SC_SMEM_BYTES>>>(p_qh, p_kh, gate, mask, attn_ptr, p_part);

    // 3) partials -> 1/rowsum
    reduce_inv<<<256, 256>>>(p_part, p_inv);

    // 4) AV: normalize attn in place (single write) + ctx
    av_v2<<<dim3(16, ZH), 256>>>(attn_ptr, p_inv, p_vh, p_ctx);

    // 5) FC projection
    gemm_v2<<<dim3(16, 32), 256, GEMM_SMEM_BYTES>>>(p_ctx, w_fc, b_fc, p_fc, DMOD, DMOD, DMOD);

    // 6) Residual + LayerNorm -> final out
    ln_kernel<<<4096, 256>>>(q, ln_g, ln_b, p_fc, out_ptr);
}

// round 7
// speedup vs baseline: 1.2146x; 1.0002x over previous
#include <cuda_runtime.h>
#include <math.h>

// Problem constants
#define BB 4
#define LS 1024
#define DMOD 1024
#define NH 16
#define DKH 64
#define DVH 64
#define ZH (BB * NH)

#define OUT_ELEMS ((long long)BB * LS * DMOD)            // 4194304
#define ATT_ELEMS ((long long)ZH * LS * LS)              // 67108864

// -------------------- scratch (device globals; no allocation allowed) ------
__device__ float g_qh[ZH * LS * DKH];        // [B,H,L,DK]
__device__ float g_kh[ZH * LS * DKH];
__device__ float g_vh[ZH * LS * DVH];
__device__ float g_ctx[BB * LS * NH * DVH];  // [B,L,H*DV]
__device__ float g_fc[BB * LS * DMOD];       // pre-LN fc output
__device__ float g_part[(size_t)ZH * LS * 16]; // per-(z,row) partial exp sums
__device__ float g_invsum[ZH * LS];          // 1 / rowsum
__device__ float g_attn[(size_t)ZH * LS * LS]; // attn scratch (fallback)
__device__ float g_outs[BB * LS * DMOD];     // fallback out sink

// ---------------------------------------------------------------------------
// helpers
// ---------------------------------------------------------------------------
__device__ __forceinline__ unsigned f2tf(float f) {
    unsigned r;
    asm("cvt.rna.tf32.f32 %0, %1;" : "=r"(r) : "f"(f));
    return r;
}

__device__ __forceinline__ void mma8(float& c0, float& c1, float& c2, float& c3,
                                     unsigned a0, unsigned a1, unsigned a2, unsigned a3,
                                     unsigned b0, unsigned b1) {
    asm volatile(
        "mma.sync.aligned.m16n8k8.row.col.f32.tf32.tf32.f32 "
        "{%0,%1,%2,%3}, {%4,%5,%6,%7}, {%8,%9}, {%0,%1,%2,%3};\n"
        : "+f"(c0), "+f"(c1), "+f"(c2), "+f"(c3)
        : "r"(a0), "r"(a1), "r"(a2), "r"(a3), "r"(b0), "r"(b1));
}

__device__ __forceinline__ void cpa16(void* s, const void* g) {
    asm volatile("cp.async.cg.shared.global [%0], [%1], 16;\n"
        :: "r"((unsigned)__cvta_generic_to_shared(s)), "l"(g) : "memory");
}
__device__ __forceinline__ void cpa_commit() {
    asm volatile("cp.async.commit_group;\n" ::: "memory");
}
template <int N> __device__ __forceinline__ void cpa_wait() {
    asm volatile("cp.async.wait_group %0;\n" :: "n"(N) : "memory");
}

// ---------------------------------------------------------------------------
// TF32 NT GEMM + bias, cp.async double-buffered.
// Tile 128(m) x 64(n), BK=32, 256 threads (8 warps, 4m x 2n, warp 32x32).
// ---------------------------------------------------------------------------
#define GEMM_SMEM_BYTES ((2 * 128 * 36 + 2 * 64 * 36) * 4)

__global__ void __launch_bounds__(256, 2)
gemm_v2(const float* __restrict__ A, const float* __restrict__ W,
        const float* __restrict__ bias, float* __restrict__ out,
        int K, int N, int Dhead)
{
    extern __shared__ float gsm[];
    float* As = gsm;
    float* Ws = gsm + 2 * 128 * 36;

    const int t = threadIdx.x, lane = t & 31, w = t >> 5;
    const int wm = w >> 1, wn = w & 1;
    const int g = lane >> 2, tg = lane & 3;
    const int rowBase = blockIdx.y * 128;
    const int colBase = blockIdx.x * 64;

    const float* Ab = A + (size_t)rowBase * K;
    const float* Wb = W + (size_t)colBase * K;

    float c[2][4][4];
#pragma unroll
    for (int mt = 0; mt < 2; mt++)
#pragma unroll
        for (int nt = 0; nt < 4; nt++)
#pragma unroll
            for (int i = 0; i < 4; i++) c[mt][nt][i] = 0.f;

    const int nk = K >> 5;

    {
#pragma unroll
        for (int i = 0; i < 4; i++) {
            const int idx4 = t + 256 * i;
            const int row = idx4 >> 3, c4 = (idx4 & 7) * 4;
            cpa16(&As[row * 36 + c4], Ab + (size_t)row * K + c4);
        }
#pragma unroll
        for (int i = 0; i < 2; i++) {
            const int idx4 = t + 256 * i;
            const int row = idx4 >> 3, c4 = (idx4 & 7) * 4;
            cpa16(&Ws[row * 36 + c4], Wb + (size_t)row * K + c4);
        }
        cpa_commit();
    }

    for (int kt = 0; kt < nk; kt++) {
        if (kt + 1 < nk) {
            float* Ad = As + ((kt + 1) & 1) * (128 * 36);
            float* Wd = Ws + ((kt + 1) & 1) * (64 * 36);
            const int ko = (kt + 1) * 32;
#pragma unroll
            for (int i = 0; i < 4; i++) {
                const int idx4 = t + 256 * i;
                const int row = idx4 >> 3, c4 = (idx4 & 7) * 4;
                cpa16(&Ad[row * 36 + c4], Ab + (size_t)row * K + ko + c4);
            }
#pragma unroll
            for (int i = 0; i < 2; i++) {
                const int idx4 = t + 256 * i;
                const int row = idx4 >> 3, c4 = (idx4 & 7) * 4;
                cpa16(&Wd[row * 36 + c4], Wb + (size_t)row * K + ko + c4);
            }
            cpa_commit();
            cpa_wait<1>();
        } else {
            cpa_wait<0>();
        }
        __syncthreads();

        const float* Ac = As + (kt & 1) * (128 * 36);
        const float* Wc = Ws + (kt & 1) * (64 * 36);
#pragma unroll
        for (int ks = 0; ks < 4; ks++) {
            const int kk = ks * 8;
            unsigned a[2][4], bf[4][2];
#pragma unroll
            for (int mt = 0; mt < 2; mt++) {
                const int r = (wm * 32 + mt * 16 + g) * 36 + kk + tg;
                a[mt][0] = f2tf(Ac[r]);
                a[mt][1] = f2tf(Ac[r + 8 * 36]);
                a[mt][2] = f2tf(Ac[r + 4]);
                a[mt][3] = f2tf(Ac[r + 8 * 36 + 4]);
            }
#pragma unroll
            for (int nt = 0; nt < 4; nt++) {
                const int r = (wn * 32 + nt * 8 + g) * 36 + kk + tg;
                bf[nt][0] = f2tf(Wc[r]);
                bf[nt][1] = f2tf(Wc[r + 4]);
            }
#pragma unroll
            for (int mt = 0; mt < 2; mt++)
#pragma unroll
                for (int nt = 0; nt < 4; nt++)
                    mma8(c[mt][nt][0], c[mt][nt][1], c[mt][nt][2], c[mt][nt][3],
                         a[mt][0], a[mt][1], a[mt][2], a[mt][3],
                         bf[nt][0], bf[nt][1]);
        }
        __syncthreads();
    }

    const int H = N / Dhead;
#pragma unroll
    for (int mt = 0; mt < 2; mt++) {
        const int rr = rowBase + wm * 32 + mt * 16 + g;
        const int b_ = rr >> 10, l = rr & 1023;
#pragma unroll
        for (int nt = 0; nt < 4; nt++) {
            const int cc = colBase + wn * 32 + nt * 8 + 2 * tg;
            const int h = cc / Dhead, d = cc % Dhead;
            const size_t dst = (((size_t)(b_ * H + h)) * LS + l) * Dhead + d;
            const float b0 = bias[cc], b1 = bias[cc + 1];
            *(float2*)&out[dst]             = make_float2(c[mt][nt][0] + b0, c[mt][nt][1] + b1);
            *(float2*)&out[dst + 8 * Dhead] = make_float2(c[mt][nt][2] + b0, c[mt][nt][3] + b1);
        }
    }
}

// ---------------------------------------------------------------------------
// Scores v3: tile 128(q) x 64(k).  MMA, then S staged through smem (aliasing
// Q staging) and a fully COALESCED gate/mask/exp/attn epilogue (float4/int4,
// one row per half-warp).  Row-sum partials via 16-lane shuffle.
// 256 threads (8 warps, 4m x 2n, warp 32x32).  grid (16, 8, 64).
// Dynamic smem: (128*68 + 64*68)*4 = 52224 B.  2 CTAs/SM.
// ---------------------------------------------------------------------------
#define SC_SMEM_BYTES ((128 * 68 + 64 * 68) * 4)

__global__ void __launch_bounds__(256, 2)
scores_v3(const float* __restrict__ qh, const float* __restrict__ kh,
          const float* __restrict__ gate, const int* __restrict__ mask,
          float* __restrict__ attn, float* __restrict__ part)
{
    extern __shared__ float ssm[];
    float* Qs  = ssm;                  // 128 x 68 (later aliased as Ss)
    float* Ksm = ssm + 128 * 68;       // 64 x 68  (later aliased as redsh)

    const int t = threadIdx.x, lane = t & 31, w = t >> 5;
    const int wm = w >> 1, wn = w & 1;
    const int g = lane >> 2, tg = lane & 3;
    const int z = blockIdx.z, b = z >> 4;
    const int qBase = blockIdx.y * 128;
    const int kBase = blockIdx.x * 64;

    const float* Q  = qh + (size_t)z * LS * DKH + (size_t)qBase * DKH;
    const float* Kp = kh + (size_t)z * LS * DKH + (size_t)kBase * DKH;

    // stage Q (128x64) and K (64x64) via cp.async
#pragma unroll
    for (int i = 0; i < 8; i++) {
        const int idx4 = t + 256 * i;
        const int row = idx4 >> 4, c = (idx4 & 15) * 4;
        cpa16(&Qs[row * 68 + c], Q + (size_t)row * DKH + c);
    }
#pragma unroll
    for (int i = 0; i < 4; i++) {
        const int idx4 = t + 256 * i;
        const int row = idx4 >> 4, c = (idx4 & 15) * 4;
        cpa16(&Ksm[row * 68 + c], Kp + (size_t)row * DKH + c);
    }
    cpa_commit();
    cpa_wait<0>();
    __syncthreads();

    float s[2][4][4];
#pragma unroll
    for (int mt = 0; mt < 2; mt++)
#pragma unroll
        for (int nt = 0; nt < 4; nt++)
#pragma unroll
            for (int i = 0; i < 4; i++) s[mt][nt][i] = 0.f;

#pragma unroll
    for (int ks = 0; ks < 8; ks++) {
        const int kk = ks * 8;
        unsigned a[2][4], bf[4][2];
#pragma unroll
        for (int mt = 0; mt < 2; mt++) {
            const int r = (wm * 32 + mt * 16 + g) * 68 + kk + tg;
            a[mt][0] = f2tf(Qs[r]);
            a[mt][1] = f2tf(Qs[r + 8 * 68]);
            a[mt][2] = f2tf(Qs[r + 4]);
            a[mt][3] = f2tf(Qs[r + 8 * 68 + 4]);
        }
#pragma unroll
        for (int nt = 0; nt < 4; nt++) {
            const int r = (wn * 32 + nt * 8 + g) * 68 + kk + tg;
            bf[nt][0] = f2tf(Ksm[r]);
            bf[nt][1] = f2tf(Ksm[r + 4]);
        }
#pragma unroll
        for (int mt = 0; mt < 2; mt++)
#pragma unroll
            for (int nt = 0; nt < 4; nt++)
                mma8(s[mt][nt][0], s[mt][nt][1], s[mt][nt][2], s[mt][nt][3],
                     a[mt][0], a[mt][1], a[mt][2], a[mt][3],
                     bf[nt][0], bf[nt][1]);
    }

    __syncthreads();   // Q/K smem reads done; safe to alias

    // stage S into smem (alias of Qs): 128 rows x 64 cols, stride 68
    float* Ss = Qs;
#pragma unroll
    for (int mt = 0; mt < 2; mt++) {
        const int row = wm * 32 + mt * 16 + g;
#pragma unroll
        for (int nt = 0; nt < 4; nt++) {
            const int col = wn * 32 + nt * 8 + 2 * tg;
            *(float2*)&Ss[row * 68 + col]       = make_float2(s[mt][nt][0], s[mt][nt][1]);
            *(float2*)&Ss[(row + 8) * 68 + col] = make_float2(s[mt][nt][2], s[mt][nt][3]);
        }
    }
    __syncthreads();

    // coalesced epilogue: one row per half-warp per i
    float* redsh = Ksm;
#pragma unroll
    for (int i = 0; i < 8; i++) {
        const int f4 = t + 256 * i;            // 2048 float4s total
        const int row = f4 >> 4, c4 = (f4 & 15) * 4;
        const int rr = qBase + row, cc = kBase + c4;
        float4 sv = *(float4*)&Ss[row * 68 + c4];
        const size_t gi = (size_t)z * LS * LS + (size_t)rr * LS + cc;
        const size_t mi = (size_t)b * LS * LS + (size_t)rr * LS + cc;
        float4 gv = *(const float4*)&gate[gi];
        int4   mv = *(const int4*)&mask[mi];
        float4 ev;
        ev.x = (mv.x > 0) ? 0.f : __expf(sv.x * 0.125f * gv.x);
        ev.y = (mv.y > 0) ? 0.f : __expf(sv.y * 0.125f * gv.y);
        ev.z = (mv.z > 0) ? 0.f : __expf(sv.z * 0.125f * gv.z);
        ev.w = (mv.w > 0) ? 0.f : __expf(sv.w * 0.125f * gv.w);
        *(float4*)&attn[gi] = ev;
        float sum = (ev.x + ev.y) + (ev.z + ev.w);
        // reduce over the 16 lanes sharing this row (lanes stay in half-warp)
        sum += __shfl_xor_sync(0xffffffffu, sum, 1);
        sum += __shfl_xor_sync(0xffffffffu, sum, 2);
        sum += __shfl_xor_sync(0xffffffffu, sum, 4);
        sum += __shfl_xor_sync(0xffffffffu, sum, 8);
        if ((lane & 15) == 0) redsh[row] = sum;   // unique row owner
    }
    __syncthreads();
    if (t < 128)
        part[((size_t)z * LS + qBase + t) * 16 + blockIdx.x] = redsh[t];
}

// ---------------------------------------------------------------------------
// Reduce 16 partials -> 1/rowsum.  grid 256, block 256.
// ---------------------------------------------------------------------------
__global__ void reduce_inv(const float* __restrict__ part, float* __restrict__ invsum)
{
    const int i = blockIdx.x * 256 + threadIdx.x;   // 65536 rows
    float s = 0.f;
#pragma unroll
    for (int j = 0; j < 16; j++) s += part[(size_t)i * 16 + j];
    invsum[i] = 1.f / s;
}

// ---------------------------------------------------------------------------
// AV v3: tile 64(q) x 64(d), BK=64 (16 outer iterations, half the syncs).
// Single-buffer P smem (register prefetch), double-buffered cp.async V.
// Normalizes P in registers; writes normalized attn back only if write_attn.
// 256 threads (8 warps, 2m x 4n, warp 32x16).  grid (16, 64).
// Dynamic smem: (64*68 + 2*64*72)*4 = 54272 B.  2 CTAs/SM.
// ---------------------------------------------------------------------------
#define AV_SMEM_BYTES ((64 * 68 + 2 * 64 * 72) * 4)

__global__ void __launch_bounds__(256, 2)
av_v3(float* __restrict__ attn, const float* __restrict__ invsum,
      const float* __restrict__ vh, float* __restrict__ ctx, int write_attn)
{
    extern __shared__ float avsm[];
    float* Ps = avsm;               // 64 x 68
    float* Vs = avsm + 64 * 68;     // 2 x (64 x 72)
    __shared__ float invsh[64];

    const int t = threadIdx.x, lane = t & 31, w = t >> 5;
    const int wm = w >> 2, wn = w & 3;     // 2m x 4n warps, warp tile 32x16
    const int g = lane >> 2, tg = lane & 3;
    const int z = blockIdx.y, b = z >> 4, h = z & 15;
    const int rowBase = blockIdx.x * 64;

    float* P = attn + (size_t)z * LS * LS + (size_t)rowBase * LS;
    const float* V = vh + (size_t)z * LS * DVH;

    if (t < 64) invsh[t] = invsum[z * LS + rowBase + t];
    __syncthreads();

    // loader coords: 4 float4 per thread per 64x64 tile
    int lr[4], lc[4];
#pragma unroll
    for (int i = 0; i < 4; i++) {
        const int idx4 = t + 256 * i;
        lr[i] = idx4 >> 4;
        lc[i] = (idx4 & 15) * 4;
    }

    float c[2][2][4];
#pragma unroll
    for (int mt = 0; mt < 2; mt++)
#pragma unroll
        for (int nt = 0; nt < 2; nt++)
#pragma unroll
            for (int i = 0; i < 4; i++) c[mt][nt][i] = 0.f;

    // prologue: V(0) async, P(0) -> regs
#pragma unroll
    for (int i = 0; i < 4; i++)
        cpa16(&Vs[lr[i] * 72 + lc[i]], V + (size_t)lr[i] * DVH + lc[i]);
    cpa_commit();
    float4 pv[4];
#pragma unroll
    for (int i = 0; i < 4; i++)
        pv[i] = *(const float4*)(P + (size_t)lr[i] * LS + lc[i]);

    for (int kt = 0; kt < 16; kt++) {
        float4 nv[4];
        const bool more = (kt + 1 < 16);
        if (more) {
            const int ko = (kt + 1) * 64;
            float* Vd = Vs + ((kt + 1) & 1) * (64 * 72);
#pragma unroll
            for (int i = 0; i < 4; i++)
                cpa16(&Vd[lr[i] * 72 + lc[i]], V + (size_t)(ko + lr[i]) * DVH + lc[i]);
            cpa_commit();
#pragma unroll
            for (int i = 0; i < 4; i++)
                nv[i] = *(const float4*)(P + (size_t)lr[i] * LS + ko + lc[i]);
        }

        __syncthreads();   // previous MMA finished reading Ps

        // normalize current P regs, optional attn write-back, stage to smem
        {
            const int ko = kt * 64;
#pragma unroll
            for (int i = 0; i < 4; i++) {
                const float iv = invsh[lr[i]];
                pv[i].x *= iv; pv[i].y *= iv; pv[i].z *= iv; pv[i].w *= iv;
                if (write_attn)
                    *(float4*)(P + (size_t)lr[i] * LS + ko + lc[i]) = pv[i];
                *(float4*)&Ps[lr[i] * 68 + lc[i]] = pv[i];
            }
        }

        if (more) cpa_wait<1>(); else cpa_wait<0>();
        __syncthreads();

        const float* Vc = Vs + (kt & 1) * (64 * 72);
#pragma unroll
        for (int ks = 0; ks < 8; ks++) {
            const int kk = ks * 8;
            unsigned a[2][4], bf[2][2];
#pragma unroll
            for (int mt = 0; mt < 2; mt++) {
                const int r = (wm * 32 + mt * 16 + g) * 68 + kk + tg;
                a[mt][0] = f2tf(Ps[r]);
                a[mt][1] = f2tf(Ps[r + 8 * 68]);
                a[mt][2] = f2tf(Ps[r + 4]);
                a[mt][3] = f2tf(Ps[r + 8 * 68 + 4]);
            }
#pragma unroll
            for (int nt = 0; nt < 2; nt++) {
                const int col = wn * 16 + nt * 8 + g;
                bf[nt][0] = f2tf(Vc[(kk + tg) * 72 + col]);
                bf[nt][1] = f2tf(Vc[(kk + tg + 4) * 72 + col]);
            }
#pragma unroll
            for (int mt = 0; mt < 2; mt++)
#pragma unroll
                for (int nt = 0; nt < 2; nt++)
                    mma8(c[mt][nt][0], c[mt][nt][1], c[mt][nt][2], c[mt][nt][3],
                         a[mt][0], a[mt][1], a[mt][2], a[mt][3],
                         bf[nt][0], bf[nt][1]);
        }
#pragma unroll
        for (int i = 0; i < 4; i++) pv[i] = nv[i];
    }

#pragma unroll
    for (int mt = 0; mt < 2; mt++) {
        const int rr = rowBase + wm * 32 + mt * 16 + g;
#pragma unroll
        for (int nt = 0; nt < 2; nt++) {
            const int d = wn * 16 + nt * 8 + 2 * tg;
            const size_t dst = ((size_t)(b * LS + rr)) * DMOD + h * 64 + d;
            *(float2*)&ctx[dst]            = make_float2(c[mt][nt][0], c[mt][nt][1]);
            *(float2*)&ctx[dst + 8 * DMOD] = make_float2(c[mt][nt][2], c[mt][nt][3]);
        }
    }
}

// ---------------------------------------------------------------------------
// Residual + LayerNorm.  grid 4096, block 256.
// ---------------------------------------------------------------------------
__global__ void ln_kernel(const float* __restrict__ resid,
                          const float* __restrict__ gamma,
                          const float* __restrict__ beta,
                          const float* __restrict__ fcv,
                          float* __restrict__ out)
{
    __shared__ float red[256];
    const int r = blockIdx.x;
    const float* xf = fcv + (size_t)r * DMOD;
    const float* rz = resid + (size_t)r * DMOD;
    const int t = threadIdx.x;

    float v[4];
    float sum = 0.f;
#pragma unroll
    for (int j = 0; j < 4; j++) {
        v[j] = xf[t + 256 * j] + rz[t + 256 * j];
        sum += v[j];
    }
    red[t] = sum; __syncthreads();
    for (int s = 128; s > 0; s >>= 1) {
        if (t < s) red[t] += red[t + s];
        __syncthreads();
    }
    const float mu = red[0] * (1.f / DMOD);
    __syncthreads();

    float vs = 0.f;
#pragma unroll
    for (int j = 0; j < 4; j++) {
        const float d = v[j] - mu;
        vs += d * d;
    }
    red[t] = vs; __syncthreads();
    for (int s = 128; s > 0; s >>= 1) {
        if (t < s) red[t] += red[t + s];
        __syncthreads();
    }
    const float var = red[0] * (1.f / DMOD);
    const float inv = rsqrtf(var + 1e-5f);
#pragma unroll
    for (int j = 0; j < 4; j++) {
        const int cc = t + 256 * j;
        out[(size_t)r * DMOD + cc] = (v[j] - mu) * inv * gamma[cc] + beta[cc];
    }
}

// ---------------------------------------------------------------------------
extern "C" void kernel_launch(void* const* d_in, const int* in_sizes, int n_in,
                              void* d_out, int out_size)
{
    const float* q    = (const float*)d_in[0];
    const float* k    = (const float*)d_in[1];
    const float* v    = (const float*)d_in[2];
    const int*   mask = (const int*)  d_in[3];
    const float* gate = (const float*)d_in[4];
    const float* w_q  = (const float*)d_in[5];
    const float* b_q  = (const float*)d_in[6];
    const float* w_k  = (const float*)d_in[7];
    const float* b_k  = (const float*)d_in[8];
    const float* w_v  = (const float*)d_in[9];
    const float* b_v  = (const float*)d_in[10];
    const float* w_fc = (const float*)d_in[11];
    const float* b_fc = (const float*)d_in[12];
    const float* ln_g = (const float*)d_in[13];
    const float* ln_b = (const float*)d_in[14];
    float* out = (float*)d_out;

    float *p_qh, *p_kh, *p_vh, *p_ctx, *p_fc, *p_part, *p_inv, *p_attn_s, *p_outs;
    cudaGetSymbolAddress((void**)&p_qh,     g_qh);
    cudaGetSymbolAddress((void**)&p_kh,     g_kh);
    cudaGetSymbolAddress((void**)&p_vh,     g_vh);
    cudaGetSymbolAddress((void**)&p_ctx,    g_ctx);
    cudaGetSymbolAddress((void**)&p_fc,     g_fc);
    cudaGetSymbolAddress((void**)&p_part,   g_part);
    cudaGetSymbolAddress((void**)&p_inv,    g_invsum);
    cudaGetSymbolAddress((void**)&p_attn_s, g_attn);
    cudaGetSymbolAddress((void**)&p_outs,   g_outs);

    // Reference returns (out, attn).  Resolve destinations from out_size.
    float* attn_ptr;
    float* out_ptr;
    const long long osz = (long long)out_size;
    if (osz >= OUT_ELEMS + ATT_ELEMS) {        // concatenated tuple
        out_ptr  = out;
        attn_ptr = out + OUT_ELEMS;
    } else if (osz >= ATT_ELEMS) {             // attn only
        out_ptr  = p_outs;
        attn_ptr = out;
    } else {                                   // out only
        out_ptr  = out;
        attn_ptr = p_attn_s;
    }
    const int write_attn = (attn_ptr != p_attn_s) ? 1 : 0;

    // opt in to >48KB dynamic smem (idempotent)
    cudaFuncSetAttribute(gemm_v2, cudaFuncAttributeMaxDynamicSharedMemorySize,
                         GEMM_SMEM_BYTES);
    cudaFuncSetAttribute(scores_v3, cudaFuncAttributeMaxDynamicSharedMemorySize,
                         SC_SMEM_BYTES);
    cudaFuncSetAttribute(av_v3, cudaFuncAttributeMaxDynamicSharedMemorySize,
                         AV_SMEM_BYTES);

    // 1) QKV projections
    gemm_v2<<<dim3(16, 32), 256, GEMM_SMEM_BYTES>>>(q, w_q, b_q, p_qh, DMOD, NH * DKH, DKH);
    gemm_v2<<<dim3(16, 32), 256, GEMM_SMEM_BYTES>>>(k, w_k, b_k, p_kh, DMOD, NH * DKH, DKH);
    gemm_v2<<<dim3(16, 32), 256, GEMM_SMEM_BYTES>>>(v, w_v, b_v, p_vh, DMOD, NH * DVH, DVH);

    // 2) Scores + gate/mask + exp + partial row sums (unnormalized attn)
    scores_v3<<<dim3(16, 8, ZH), 256, SC_SMEM_BYTES>>>(p_qh, p_kh, gate, mask, attn_ptr, p_part);

    // 3) partials -> 1/rowsum
    reduce_inv<<<256, 256>>>(p_part, p_inv);

    // 4) AV: normalize attn (write back only if attn is a real output) + ctx
    av_v3<<<dim3(16, ZH), 256, AV_SMEM_BYTES>>>(attn_ptr, p_inv, p_vh, p_ctx, write_attn);

    // 5) FC projection
    gemm_v2<<<dim3(16, 32), 256, GEMM_SMEM_BYTES>>>(p_ctx, w_fc, b_fc, p_fc, DMOD, DMOD, DMOD);

    // 6) Residual + LayerNorm -> final out
    ln_kernel<<<4096, 256>>>(q, ln_g, ln_b, p_fc, out_ptr);
}

// round 8
// speedup vs baseline: 1.3318x; 1.0965x over previous
#include <cuda_runtime.h>
#include <math.h>

// Problem constants
#define BB 4
#define LS 1024
#define DMOD 1024
#define NH 16
#define DKH 64
#define DVH 64
#define ZH (BB * NH)

#define OUT_ELEMS ((long long)BB * LS * DMOD)            // 4194304
#define ATT_ELEMS ((long long)ZH * LS * LS)              // 67108864

// -------------------- scratch (device globals; no allocation allowed) ------
__device__ float g_qh[ZH * LS * DKH];        // [B,H,L,DK]
__device__ float g_kh[ZH * LS * DKH];
__device__ float g_vh[ZH * LS * DVH];
__device__ float g_ctx[BB * LS * NH * DVH];  // [B,L,H*DV]
__device__ float g_fc[BB * LS * DMOD];       // pre-LN fc output
__device__ float g_part[(size_t)ZH * LS * 16]; // per-(z,row) partial exp sums
__device__ float g_invsum[ZH * LS];          // 1 / rowsum
__device__ float g_attn[(size_t)ZH * LS * LS]; // attn scratch (fallback)
__device__ float g_outs[BB * LS * DMOD];     // fallback out sink

// ---------------------------------------------------------------------------
// helpers
// ---------------------------------------------------------------------------
__device__ __forceinline__ unsigned f2tf(float f) {
    unsigned r;
    asm("cvt.rna.tf32.f32 %0, %1;" : "=r"(r) : "f"(f));
    return r;
}

__device__ __forceinline__ void mma8(float& c0, float& c1, float& c2, float& c3,
                                     unsigned a0, unsigned a1, unsigned a2, unsigned a3,
                                     unsigned b0, unsigned b1) {
    asm volatile(
        "mma.sync.aligned.m16n8k8.row.col.f32.tf32.tf32.f32 "
        "{%0,%1,%2,%3}, {%4,%5,%6,%7}, {%8,%9}, {%0,%1,%2,%3};\n"
        : "+f"(c0), "+f"(c1), "+f"(c2), "+f"(c3)
        : "r"(a0), "r"(a1), "r"(a2), "r"(a3), "r"(b0), "r"(b1));
}

__device__ __forceinline__ void cpa16(void* s, const void* g) {
    asm volatile("cp.async.cg.shared.global [%0], [%1], 16;\n"
        :: "r"((unsigned)__cvta_generic_to_shared(s)), "l"(g) : "memory");
}
__device__ __forceinline__ void cpa_commit() {
    asm volatile("cp.async.commit_group;\n" ::: "memory");
}
template <int N> __device__ __forceinline__ void cpa_wait() {
    asm volatile("cp.async.wait_group %0;\n" :: "n"(N) : "memory");
}

// ---------------------------------------------------------------------------
// TF32 NT GEMM + bias, cp.async double-buffered (unchanged — known good).
// Tile 128(m) x 64(n), BK=32, 256 threads (8 warps, 4m x 2n, warp 32x32).
// ---------------------------------------------------------------------------
#define GEMM_SMEM_BYTES ((2 * 128 * 36 + 2 * 64 * 36) * 4)

__global__ void __launch_bounds__(256, 2)
gemm_v2(const float* __restrict__ A, const float* __restrict__ W,
        const float* __restrict__ bias, float* __restrict__ out,
        int K, int N, int Dhead)
{
    extern __shared__ float gsm[];
    float* As = gsm;
    float* Ws = gsm + 2 * 128 * 36;

    const int t = threadIdx.x, lane = t & 31, w = t >> 5;
    const int wm = w >> 1, wn = w & 1;
    const int g = lane >> 2, tg = lane & 3;
    const int rowBase = blockIdx.y * 128;
    const int colBase = blockIdx.x * 64;

    const float* Ab = A + (size_t)rowBase * K;
    const float* Wb = W + (size_t)colBase * K;

    float c[2][4][4];
#pragma unroll
    for (int mt = 0; mt < 2; mt++)
#pragma unroll
        for (int nt = 0; nt < 4; nt++)
#pragma unroll
            for (int i = 0; i < 4; i++) c[mt][nt][i] = 0.f;

    const int nk = K >> 5;

    {
#pragma unroll
        for (int i = 0; i < 4; i++) {
            const int idx4 = t + 256 * i;
            const int row = idx4 >> 3, c4 = (idx4 & 7) * 4;
            cpa16(&As[row * 36 + c4], Ab + (size_t)row * K + c4);
        }
#pragma unroll
        for (int i = 0; i < 2; i++) {
            const int idx4 = t + 256 * i;
            const int row = idx4 >> 3, c4 = (idx4 & 7) * 4;
            cpa16(&Ws[row * 36 + c4], Wb + (size_t)row * K + c4);
        }
        cpa_commit();
    }

    for (int kt = 0; kt < nk; kt++) {
        if (kt + 1 < nk) {
            float* Ad = As + ((kt + 1) & 1) * (128 * 36);
            float* Wd = Ws + ((kt + 1) & 1) * (64 * 36);
            const int ko = (kt + 1) * 32;
#pragma unroll
            for (int i = 0; i < 4; i++) {
                const int idx4 = t + 256 * i;
                const int row = idx4 >> 3, c4 = (idx4 & 7) * 4;
                cpa16(&Ad[row * 36 + c4], Ab + (size_t)row * K + ko + c4);
            }
#pragma unroll
            for (int i = 0; i < 2; i++) {
                const int idx4 = t + 256 * i;
                const int row = idx4 >> 3, c4 = (idx4 & 7) * 4;
                cpa16(&Wd[row * 36 + c4], Wb + (size_t)row * K + ko + c4);
            }
            cpa_commit();
            cpa_wait<1>();
        } else {
            cpa_wait<0>();
        }
        __syncthreads();

        const float* Ac = As + (kt & 1) * (128 * 36);
        const float* Wc = Ws + (kt & 1) * (64 * 36);
#pragma unroll
        for (int ks = 0; ks < 4; ks++) {
            const int kk = ks * 8;
            unsigned a[2][4], bf[4][2];
#pragma unroll
            for (int mt = 0; mt < 2; mt++) {
                const int r = (wm * 32 + mt * 16 + g) * 36 + kk + tg;
                a[mt][0] = f2tf(Ac[r]);
                a[mt][1] = f2tf(Ac[r + 8 * 36]);
                a[mt][2] = f2tf(Ac[r + 4]);
                a[mt][3] = f2tf(Ac[r + 8 * 36 + 4]);
            }
#pragma unroll
            for (int nt = 0; nt < 4; nt++) {
                const int r = (wn * 32 + nt * 8 + g) * 36 + kk + tg;
                bf[nt][0] = f2tf(Wc[r]);
                bf[nt][1] = f2tf(Wc[r + 4]);
            }
#pragma unroll
            for (int mt = 0; mt < 2; mt++)
#pragma unroll
                for (int nt = 0; nt < 4; nt++)
                    mma8(c[mt][nt][0], c[mt][nt][1], c[mt][nt][2], c[mt][nt][3],
                         a[mt][0], a[mt][1], a[mt][2], a[mt][3],
                         bf[nt][0], bf[nt][1]);
        }
        __syncthreads();
    }

    const int H = N / Dhead;
#pragma unroll
    for (int mt = 0; mt < 2; mt++) {
        const int rr = rowBase + wm * 32 + mt * 16 + g;
        const int b_ = rr >> 10, l = rr & 1023;
#pragma unroll
        for (int nt = 0; nt < 4; nt++) {
            const int cc = colBase + wn * 32 + nt * 8 + 2 * tg;
            const int h = cc / Dhead, d = cc % Dhead;
            const size_t dst = (((size_t)(b_ * H + h)) * LS + l) * Dhead + d;
            const float b0 = bias[cc], b1 = bias[cc + 1];
            *(float2*)&out[dst]             = make_float2(c[mt][nt][0] + b0, c[mt][nt][1] + b1);
            *(float2*)&out[dst + 8 * Dhead] = make_float2(c[mt][nt][2] + b0, c[mt][nt][3] + b1);
        }
    }
}

// ---------------------------------------------------------------------------
// Scores v4: tile 64(q) x 64(k) for 3 CTAs/SM occupancy.
// MMA, then S staged through smem (aliasing Q) and a fully coalesced
// gate/mask/exp/attn epilogue.  Row-sum partials via 16-lane shuffle.
// 256 threads (8 warps, 2m x 4n, warp 32x16).  grid (16, 16, 64).
// Dynamic smem: 2*64*68*4 = 34816 B.  3 CTAs/SM (reg-capped).
// ---------------------------------------------------------------------------
#define SC_SMEM_BYTES (2 * 64 * 68 * 4)

__global__ void __launch_bounds__(256, 3)
scores_v4(const float* __restrict__ qh, const float* __restrict__ kh,
          const float* __restrict__ gate, const int* __restrict__ mask,
          float* __restrict__ attn, float* __restrict__ part)
{
    extern __shared__ float ssm[];
    float* Qs  = ssm;                  // 64 x 68 (later aliased as Ss)
    float* Ksm = ssm + 64 * 68;        // 64 x 68 (later aliased as redsh)

    const int t = threadIdx.x, lane = t & 31, w = t >> 5;
    const int wm = w >> 2, wn = w & 3;     // 2m x 4n warps, warp tile 32x16
    const int g = lane >> 2, tg = lane & 3;
    const int z = blockIdx.z, b = z >> 4;
    const int qBase = blockIdx.y * 64;
    const int kBase = blockIdx.x * 64;

    const float* Q  = qh + (size_t)z * LS * DKH + (size_t)qBase * DKH;
    const float* Kp = kh + (size_t)z * LS * DKH + (size_t)kBase * DKH;

    // stage Q (64x64) and K (64x64) via cp.async: 4 float4 each per thread
#pragma unroll
    for (int i = 0; i < 4; i++) {
        const int idx4 = t + 256 * i;
        const int row = idx4 >> 4, c = (idx4 & 15) * 4;
        cpa16(&Qs[row * 68 + c], Q + (size_t)row * DKH + c);
        cpa16(&Ksm[row * 68 + c], Kp + (size_t)row * DKH + c);
    }
    cpa_commit();
    cpa_wait<0>();
    __syncthreads();

    float s[2][2][4];
#pragma unroll
    for (int mt = 0; mt < 2; mt++)
#pragma unroll
        for (int nt = 0; nt < 2; nt++)
#pragma unroll
            for (int i = 0; i < 4; i++) s[mt][nt][i] = 0.f;

#pragma unroll
    for (int ks = 0; ks < 8; ks++) {
        const int kk = ks * 8;
        unsigned a[2][4], bf[2][2];
#pragma unroll
        for (int mt = 0; mt < 2; mt++) {
            const int r = (wm * 32 + mt * 16 + g) * 68 + kk + tg;
            a[mt][0] = f2tf(Qs[r]);
            a[mt][1] = f2tf(Qs[r + 8 * 68]);
            a[mt][2] = f2tf(Qs[r + 4]);
            a[mt][3] = f2tf(Qs[r + 8 * 68 + 4]);
        }
#pragma unroll
        for (int nt = 0; nt < 2; nt++) {
            const int r = (wn * 16 + nt * 8 + g) * 68 + kk + tg;
            bf[nt][0] = f2tf(Ksm[r]);
            bf[nt][1] = f2tf(Ksm[r + 4]);
        }
#pragma unroll
        for (int mt = 0; mt < 2; mt++)
#pragma unroll
            for (int nt = 0; nt < 2; nt++)
                mma8(s[mt][nt][0], s[mt][nt][1], s[mt][nt][2], s[mt][nt][3],
                     a[mt][0], a[mt][1], a[mt][2], a[mt][3],
                     bf[nt][0], bf[nt][1]);
    }

    __syncthreads();   // Q/K smem reads done; safe to alias

    // stage S into smem (alias of Qs): 64 rows x 64 cols, stride 68
    float* Ss = Qs;
#pragma unroll
    for (int mt = 0; mt < 2; mt++) {
        const int row = wm * 32 + mt * 16 + g;
#pragma unroll
        for (int nt = 0; nt < 2; nt++) {
            const int col = wn * 16 + nt * 8 + 2 * tg;
            *(float2*)&Ss[row * 68 + col]       = make_float2(s[mt][nt][0], s[mt][nt][1]);
            *(float2*)&Ss[(row + 8) * 68 + col] = make_float2(s[mt][nt][2], s[mt][nt][3]);
        }
    }
    __syncthreads();

    // coalesced epilogue: 1024 float4s, one row per 16 consecutive threads
    float* redsh = Ksm;
#pragma unroll
    for (int i = 0; i < 4; i++) {
        const int f4 = t + 256 * i;
        const int row = f4 >> 4, c4 = (f4 & 15) * 4;
        const int rr = qBase + row, cc = kBase + c4;
        float4 sv = *(float4*)&Ss[row * 68 + c4];
        const size_t gi = (size_t)z * LS * LS + (size_t)rr * LS + cc;
        const size_t mi = (size_t)b * LS * LS + (size_t)rr * LS + cc;
        float4 gv = *(const float4*)&gate[gi];
        int4   mv = *(const int4*)&mask[mi];
        float4 ev;
        ev.x = (mv.x > 0) ? 0.f : __expf(sv.x * 0.125f * gv.x);
        ev.y = (mv.y > 0) ? 0.f : __expf(sv.y * 0.125f * gv.y);
        ev.z = (mv.z > 0) ? 0.f : __expf(sv.z * 0.125f * gv.z);
        ev.w = (mv.w > 0) ? 0.f : __expf(sv.w * 0.125f * gv.w);
        *(float4*)&attn[gi] = ev;
        float sum = (ev.x + ev.y) + (ev.z + ev.w);
        sum += __shfl_xor_sync(0xffffffffu, sum, 1);
        sum += __shfl_xor_sync(0xffffffffu, sum, 2);
        sum += __shfl_xor_sync(0xffffffffu, sum, 4);
        sum += __shfl_xor_sync(0xffffffffu, sum, 8);
        if ((lane & 15) == 0) redsh[row] = sum;   // unique row owner
    }
    __syncthreads();
    if (t < 64)
        part[((size_t)z * LS + qBase + t) * 16 + blockIdx.x] = redsh[t];
}

// ---------------------------------------------------------------------------
// Reduce 16 partials -> 1/rowsum.  grid 256, block 256.
// ---------------------------------------------------------------------------
__global__ void reduce_inv(const float* __restrict__ part, float* __restrict__ invsum)
{
    const int i = blockIdx.x * 256 + threadIdx.x;   // 65536 rows
    float s = 0.f;
#pragma unroll
    for (int j = 0; j < 16; j++) s += part[(size_t)i * 16 + j];
    invsum[i] = 1.f / s;
}

// ---------------------------------------------------------------------------
// AV v4: tile 64(q) x 64(d), BK=64.  BOTH P and V staged via cp.async,
// double-buffered.  MMA on UNNORMALIZED P; ctx scaled by invsum at the end
// ((P V)/s == (P/s) V in exact fp32 scaling).  Normalized attn write-back is
// a coalesced smem->global pass, executed only when write_attn.
// 256 threads (8 warps, 2m x 4n, warp 32x16).  grid (16, 64).
// Dynamic smem: (2*64*68 + 2*64*72)*4 = 71680 B.  3 CTAs/SM.
// ---------------------------------------------------------------------------
#define AV_SMEM_BYTES ((2 * 64 * 68 + 2 * 64 * 72) * 4)

__global__ void __launch_bounds__(256, 3)
av_v4(float* __restrict__ attn, const float* __restrict__ invsum,
      const float* __restrict__ vh, float* __restrict__ ctx, int write_attn)
{
    extern __shared__ float avsm[];
    float* Ps = avsm;                   // 2 x (64 x 68)
    float* Vs = avsm + 2 * 64 * 68;     // 2 x (64 x 72)
    __shared__ float invsh[64];

    const int t = threadIdx.x, lane = t & 31, w = t >> 5;
    const int wm = w >> 2, wn = w & 3;     // 2m x 4n warps, warp tile 32x16
    const int g = lane >> 2, tg = lane & 3;
    const int z = blockIdx.y, b = z >> 4, h = z & 15;
    const int rowBase = blockIdx.x * 64;

    float* P = attn + (size_t)z * LS * LS + (size_t)rowBase * LS;
    const float* V = vh + (size_t)z * LS * DVH;

    if (t < 64) invsh[t] = invsum[z * LS + rowBase + t];

    // loader coords: 4 float4 per thread per 64x64 tile
    int lr[4], lc[4];
#pragma unroll
    for (int i = 0; i < 4; i++) {
        const int idx4 = t + 256 * i;
        lr[i] = idx4 >> 4;
        lc[i] = (idx4 & 15) * 4;
    }

    float c[2][2][4];
#pragma unroll
    for (int mt = 0; mt < 2; mt++)
#pragma unroll
        for (int nt = 0; nt < 2; nt++)
#pragma unroll
            for (int i = 0; i < 4; i++) c[mt][nt][i] = 0.f;

    // prologue: P(0), V(0) async
#pragma unroll
    for (int i = 0; i < 4; i++) {
        cpa16(&Ps[lr[i] * 68 + lc[i]], P + (size_t)lr[i] * LS + lc[i]);
        cpa16(&Vs[lr[i] * 72 + lc[i]], V + (size_t)lr[i] * DVH + lc[i]);
    }
    cpa_commit();

    for (int kt = 0; kt < 16; kt++) {
        const bool more = (kt + 1 < 16);
        if (more) {
            const int ko = (kt + 1) * 64;
            float* Pd = Ps + ((kt + 1) & 1) * (64 * 68);
            float* Vd = Vs + ((kt + 1) & 1) * (64 * 72);
#pragma unroll
            for (int i = 0; i < 4; i++) {
                cpa16(&Pd[lr[i] * 68 + lc[i]], P + (size_t)lr[i] * LS + ko + lc[i]);
                cpa16(&Vd[lr[i] * 72 + lc[i]], V + (size_t)(ko + lr[i]) * DVH + lc[i]);
            }
            cpa_commit();
            cpa_wait<1>();
        } else {
            cpa_wait<0>();
        }
        __syncthreads();

        const float* Pc = Ps + (kt & 1) * (64 * 68);
        const float* Vc = Vs + (kt & 1) * (64 * 72);

        // normalized attn write-back (coalesced), only when attn is an output
        if (write_attn) {
            const int ko = kt * 64;
#pragma unroll
            for (int i = 0; i < 4; i++) {
                float4 pv = *(const float4*)&Pc[lr[i] * 68 + lc[i]];
                const float iv = invsh[lr[i]];
                pv.x *= iv; pv.y *= iv; pv.z *= iv; pv.w *= iv;
                *(float4*)(P + (size_t)lr[i] * LS + ko + lc[i]) = pv;
            }
        }

#pragma unroll
        for (int ks = 0; ks < 8; ks++) {
            const int kk = ks * 8;
            unsigned a[2][4], bf[2][2];
#pragma unroll
            for (int mt = 0; mt < 2; mt++) {
                const int r = (wm * 32 + mt * 16 + g) * 68 + kk + tg;
                a[mt][0] = f2tf(Pc[r]);
                a[mt][1] = f2tf(Pc[r + 8 * 68]);
                a[mt][2] = f2tf(Pc[r + 4]);
                a[mt][3] = f2tf(Pc[r + 8 * 68 + 4]);
            }
#pragma unroll
            for (int nt = 0; nt < 2; nt++) {
                const int col = wn * 16 + nt * 8 + g;
                bf[nt][0] = f2tf(Vc[(kk + tg) * 72 + col]);
                bf[nt][1] = f2tf(Vc[(kk + tg + 4) * 72 + col]);
            }
#pragma unroll
            for (int mt = 0; mt < 2; mt++)
#pragma unroll
                for (int nt = 0; nt < 2; nt++)
                    mma8(c[mt][nt][0], c[mt][nt][1], c[mt][nt][2], c[mt][nt][3],
                         a[mt][0], a[mt][1], a[mt][2], a[mt][3],
                         bf[nt][0], bf[nt][1]);
        }
        __syncthreads();
    }

    // final: scale by 1/rowsum, write ctx
#pragma unroll
    for (int mt = 0; mt < 2; mt++) {
        const int lrow = wm * 32 + mt * 16 + g;
        const int rr = rowBase + lrow;
        const float iv0 = invsh[lrow], iv1 = invsh[lrow + 8];
#pragma unroll
        for (int nt = 0; nt < 2; nt++) {
            const int d = wn * 16 + nt * 8 + 2 * tg;
            const size_t dst = ((size_t)(b * LS + rr)) * DMOD + h * 64 + d;
            *(float2*)&ctx[dst]            = make_float2(c[mt][nt][0] * iv0, c[mt][nt][1] * iv0);
            *(float2*)&ctx[dst + 8 * DMOD] = make_float2(c[mt][nt][2] * iv1, c[mt][nt][3] * iv1);
        }
    }
}

// ---------------------------------------------------------------------------
// Residual + LayerNorm.  grid 4096, block 256.
// ---------------------------------------------------------------------------
__global__ void ln_kernel(const float* __restrict__ resid,
                          const float* __restrict__ gamma,
                          const float* __restrict__ beta,
                          const float* __restrict__ fcv,
                          float* __restrict__ out)
{
    __shared__ float red[256];
    const int r = blockIdx.x;
    const float* xf = fcv + (size_t)r * DMOD;
    const float* rz = resid + (size_t)r * DMOD;
    const int t = threadIdx.x;

    float v[4];
    float sum = 0.f;
#pragma unroll
    for (int j = 0; j < 4; j++) {
        v[j] = xf[t + 256 * j] + rz[t + 256 * j];
        sum += v[j];
    }
    red[t] = sum; __syncthreads();
    for (int s = 128; s > 0; s >>= 1) {
        if (t < s) red[t] += red[t + s];
        __syncthreads();
    }
    const float mu = red[0] * (1.f / DMOD);
    __syncthreads();

    float vs = 0.f;
#pragma unroll
    for (int j = 0; j < 4; j++) {
        const float d = v[j] - mu;
        vs += d * d;
    }
    red[t] = vs; __syncthreads();
    for (int s = 128; s > 0; s >>= 1) {
        if (t < s) red[t] += red[t + s];
        __syncthreads();
    }
    const float var = red[0] * (1.f / DMOD);
    const float inv = rsqrtf(var + 1e-5f);
#pragma unroll
    for (int j = 0; j < 4; j++) {
        const int cc = t + 256 * j;
        out[(size_t)r * DMOD + cc] = (v[j] - mu) * inv * gamma[cc] + beta[cc];
    }
}

// ---------------------------------------------------------------------------
extern "C" void kernel_launch(void* const* d_in, const int* in_sizes, int n_in,
                              void* d_out, int out_size)
{
    const float* q    = (const float*)d_in[0];
    const float* k    = (const float*)d_in[1];
    const float* v    = (const float*)d_in[2];
    const int*   mask = (const int*)  d_in[3];
    const float* gate = (const float*)d_in[4];
    const float* w_q  = (const float*)d_in[5];
    const float* b_q  = (const float*)d_in[6];
    const float* w_k  = (const float*)d_in[7];
    const float* b_k  = (const float*)d_in[8];
    const float* w_v  = (const float*)d_in[9];
    const float* b_v  = (const float*)d_in[10];
    const float* w_fc = (const float*)d_in[11];
    const float* b_fc = (const float*)d_in[12];
    const float* ln_g = (const float*)d_in[13];
    const float* ln_b = (const float*)d_in[14];
    float* out = (float*)d_out;

    float *p_qh, *p_kh, *p_vh, *p_ctx, *p_fc, *p_part, *p_inv, *p_attn_s, *p_outs;
    cudaGetSymbolAddress((void**)&p_qh,     g_qh);
    cudaGetSymbolAddress((void**)&p_kh,     g_kh);
    cudaGetSymbolAddress((void**)&p_vh,     g_vh);
    cudaGetSymbolAddress((void**)&p_ctx,    g_ctx);
    cudaGetSymbolAddress((void**)&p_fc,     g_fc);
    cudaGetSymbolAddress((void**)&p_part,   g_part);
    cudaGetSymbolAddress((void**)&p_inv,    g_invsum);
    cudaGetSymbolAddress((void**)&p_attn_s, g_attn);
    cudaGetSymbolAddress((void**)&p_outs,   g_outs);

    // Reference returns (out, attn).  Resolve destinations from out_size.
    float* attn_ptr;
    float* out_ptr;
    const long long osz = (long long)out_size;
    if (osz >= OUT_ELEMS + ATT_ELEMS) {        // concatenated tuple
        out_ptr  = out;
        attn_ptr = out + OUT_ELEMS;
    } else if (osz >= ATT_ELEMS) {             // attn only
        out_ptr  = p_outs;
        attn_ptr = out;
    } else {                                   // out only
        out_ptr  = out;
        attn_ptr = p_attn_s;
    }
    const int write_attn = (attn_ptr != p_attn_s) ? 1 : 0;

    // opt in to >48KB dynamic smem (idempotent)
    cudaFuncSetAttribute(gemm_v2, cudaFuncAttributeMaxDynamicSharedMemorySize,
                         GEMM_SMEM_BYTES);
    cudaFuncSetAttribute(av_v4, cudaFuncAttributeMaxDynamicSharedMemorySize,
                         AV_SMEM_BYTES);

    // 1) QKV projections
    gemm_v2<<<dim3(16, 32), 256, GEMM_SMEM_BYTES>>>(q, w_q, b_q, p_qh, DMOD, NH * DKH, DKH);
    gemm_v2<<<dim3(16, 32), 256, GEMM_SMEM_BYTES>>>(k, w_k, b_k, p_kh, DMOD, NH * DKH, DKH);
    gemm_v2<<<dim3(16, 32), 256, GEMM_SMEM_BYTES>>>(v, w_v, b_v, p_vh, DMOD, NH * DVH, DVH);

    // 2) Scores + gate/mask + exp + partial row sums (unnormalized attn)
    scores_v4<<<dim3(16, 16, ZH), 256, SC_SMEM_BYTES>>>(p_qh, p_kh, gate, mask, attn_ptr, p_part);

    // 3) partials -> 1/rowsum
    reduce_inv<<<256, 256>>>(p_part, p_inv);

    // 4) AV: MMA unnormalized P, scale ctx; conditional normalized attn write
    av_v4<<<dim3(16, ZH), 256, AV_SMEM_BYTES>>>(attn_ptr, p_inv, p_vh, p_ctx, write_attn);

    // 5) FC projection
    gemm_v2<<<dim3(16, 32), 256, GEMM_SMEM_BYTES>>>(p_ctx, w_fc, b_fc, p_fc, DMOD, DMOD, DMOD);

    // 6) Residual + LayerNorm -> final out
    ln_kernel<<<4096, 256>>>(q, ln_g, ln_b, p_fc, out_ptr);
}

// round 9
// speedup vs baseline: 1.4890x; 1.1180x over previous
#include <cuda_runtime.h>
#include <math.h>

// Problem constants
#define BB 4
#define LS 1024
#define DMOD 1024
#define NH 16
#define DKH 64
#define DVH 64
#define ZH (BB * NH)

#define OUT_ELEMS ((long long)BB * LS * DMOD)            // 4194304
#define ATT_ELEMS ((long long)ZH * LS * LS)              // 67108864

// -------------------- scratch (device globals; no allocation allowed) ------
__device__ float g_qh[ZH * LS * DKH];        // [B,H,L,DK]
__device__ float g_kh[ZH * LS * DKH];
__device__ float g_vh[ZH * LS * DVH];
__device__ float g_ctx[BB * LS * NH * DVH];  // [B,L,H*DV]
__device__ float g_fc[BB * LS * DMOD];       // pre-LN fc output
__device__ float g_part[(size_t)ZH * LS * 16]; // per-(z,row) partial exp sums
__device__ float g_invsum[ZH * LS];          // 1 / rowsum
__device__ float g_attn[(size_t)ZH * LS * LS]; // attn scratch (fallback)
__device__ float g_outs[BB * LS * DMOD];     // fallback out sink

// ---------------------------------------------------------------------------
// helpers
// ---------------------------------------------------------------------------
__device__ __forceinline__ unsigned f2tf(float f) {
    unsigned r;
    asm("cvt.rna.tf32.f32 %0, %1;" : "=r"(r) : "f"(f));
    return r;
}

__device__ __forceinline__ void mma8(float& c0, float& c1, float& c2, float& c3,
                                     unsigned a0, unsigned a1, unsigned a2, unsigned a3,
                                     unsigned b0, unsigned b1) {
    asm volatile(
        "mma.sync.aligned.m16n8k8.row.col.f32.tf32.tf32.f32 "
        "{%0,%1,%2,%3}, {%4,%5,%6,%7}, {%8,%9}, {%0,%1,%2,%3};\n"
        : "+f"(c0), "+f"(c1), "+f"(c2), "+f"(c3)
        : "r"(a0), "r"(a1), "r"(a2), "r"(a3), "r"(b0), "r"(b1));
}

__device__ __forceinline__ void cpa16(void* s, const void* g) {
    asm volatile("cp.async.cg.shared.global [%0], [%1], 16;\n"
        :: "r"((unsigned)__cvta_generic_to_shared(s)), "l"(g) : "memory");
}
__device__ __forceinline__ void cpa_commit() {
    asm volatile("cp.async.commit_group;\n" ::: "memory");
}
template <int N> __device__ __forceinline__ void cpa_wait() {
    asm volatile("cp.async.wait_group %0;\n" :: "n"(N) : "memory");
}

// ---------------------------------------------------------------------------
// TF32 NT GEMM + bias, cp.async double-buffered.
// Tile 128(m) x 64(n), BK=32, 256 threads (8 warps, 4m x 2n, warp 32x32).
// QKV-merged variant: blockIdx.z selects (A, W, bias, out) set.
// ---------------------------------------------------------------------------
#define GEMM_SMEM_BYTES ((2 * 128 * 36 + 2 * 64 * 36) * 4)

__device__ __forceinline__ void gemm_body(
    const float* __restrict__ A, const float* __restrict__ W,
    const float* __restrict__ bias, float* __restrict__ out,
    int K, int N, int Dhead, float* gsm)
{
    float* As = gsm;
    float* Ws = gsm + 2 * 128 * 36;

    const int t = threadIdx.x, lane = t & 31, w = t >> 5;
    const int wm = w >> 1, wn = w & 1;
    const int g = lane >> 2, tg = lane & 3;
    const int rowBase = blockIdx.y * 128;
    const int colBase = blockIdx.x * 64;

    const float* Ab = A + (size_t)rowBase * K;
    const float* Wb = W + (size_t)colBase * K;

    float c[2][4][4];
#pragma unroll
    for (int mt = 0; mt < 2; mt++)
#pragma unroll
        for (int nt = 0; nt < 4; nt++)
#pragma unroll
            for (int i = 0; i < 4; i++) c[mt][nt][i] = 0.f;

    const int nk = K >> 5;

    {
#pragma unroll
        for (int i = 0; i < 4; i++) {
            const int idx4 = t + 256 * i;
            const int row = idx4 >> 3, c4 = (idx4 & 7) * 4;
            cpa16(&As[row * 36 + c4], Ab + (size_t)row * K + c4);
        }
#pragma unroll
        for (int i = 0; i < 2; i++) {
            const int idx4 = t + 256 * i;
            const int row = idx4 >> 3, c4 = (idx4 & 7) * 4;
            cpa16(&Ws[row * 36 + c4], Wb + (size_t)row * K + c4);
        }
        cpa_commit();
    }

    for (int kt = 0; kt < nk; kt++) {
        if (kt + 1 < nk) {
            float* Ad = As + ((kt + 1) & 1) * (128 * 36);
            float* Wd = Ws + ((kt + 1) & 1) * (64 * 36);
            const int ko = (kt + 1) * 32;
#pragma unroll
            for (int i = 0; i < 4; i++) {
                const int idx4 = t + 256 * i;
                const int row = idx4 >> 3, c4 = (idx4 & 7) * 4;
                cpa16(&Ad[row * 36 + c4], Ab + (size_t)row * K + ko + c4);
            }
#pragma unroll
            for (int i = 0; i < 2; i++) {
                const int idx4 = t + 256 * i;
                const int row = idx4 >> 3, c4 = (idx4 & 7) * 4;
                cpa16(&Wd[row * 36 + c4], Wb + (size_t)row * K + ko + c4);
            }
            cpa_commit();
            cpa_wait<1>();
        } else {
            cpa_wait<0>();
        }
        __syncthreads();

        const float* Ac = As + (kt & 1) * (128 * 36);
        const float* Wc = Ws + (kt & 1) * (64 * 36);
#pragma unroll
        for (int ks = 0; ks < 4; ks++) {
            const int kk = ks * 8;
            unsigned a[2][4], bf[4][2];
#pragma unroll
            for (int mt = 0; mt < 2; mt++) {
                const int r = (wm * 32 + mt * 16 + g) * 36 + kk + tg;
                a[mt][0] = f2tf(Ac[r]);
                a[mt][1] = f2tf(Ac[r + 8 * 36]);
                a[mt][2] = f2tf(Ac[r + 4]);
                a[mt][3] = f2tf(Ac[r + 8 * 36 + 4]);
            }
#pragma unroll
            for (int nt = 0; nt < 4; nt++) {
                const int r = (wn * 32 + nt * 8 + g) * 36 + kk + tg;
                bf[nt][0] = f2tf(Wc[r]);
                bf[nt][1] = f2tf(Wc[r + 4]);
            }
#pragma unroll
            for (int mt = 0; mt < 2; mt++)
#pragma unroll
                for (int nt = 0; nt < 4; nt++)
                    mma8(c[mt][nt][0], c[mt][nt][1], c[mt][nt][2], c[mt][nt][3],
                         a[mt][0], a[mt][1], a[mt][2], a[mt][3],
                         bf[nt][0], bf[nt][1]);
        }
        __syncthreads();
    }

    const int H = N / Dhead;
#pragma unroll
    for (int mt = 0; mt < 2; mt++) {
        const int rr = rowBase + wm * 32 + mt * 16 + g;
        const int b_ = rr >> 10, l = rr & 1023;
#pragma unroll
        for (int nt = 0; nt < 4; nt++) {
            const int cc = colBase + wn * 32 + nt * 8 + 2 * tg;
            const int h = cc / Dhead, d = cc % Dhead;
            const size_t dst = (((size_t)(b_ * H + h)) * LS + l) * Dhead + d;
            const float b0 = bias[cc], b1 = bias[cc + 1];
            *(float2*)&out[dst]             = make_float2(c[mt][nt][0] + b0, c[mt][nt][1] + b1);
            *(float2*)&out[dst + 8 * Dhead] = make_float2(c[mt][nt][2] + b0, c[mt][nt][3] + b1);
        }
    }
}

__global__ void __launch_bounds__(256, 2)
gemm_v2(const float* __restrict__ A, const float* __restrict__ W,
        const float* __restrict__ bias, float* __restrict__ out,
        int K, int N, int Dhead)
{
    extern __shared__ float gsm[];
    gemm_body(A, W, bias, out, K, N, Dhead, gsm);
}

// merged QKV: z selects input/weight/bias/output
__global__ void __launch_bounds__(256, 2)
gemm_qkv(const float* __restrict__ q, const float* __restrict__ k,
         const float* __restrict__ v,
         const float* __restrict__ w_q, const float* __restrict__ w_k,
         const float* __restrict__ w_v,
         const float* __restrict__ b_q, const float* __restrict__ b_k,
         const float* __restrict__ b_v,
         float* __restrict__ oq, float* __restrict__ ok, float* __restrict__ ov)
{
    extern __shared__ float gsm[];
    const int zz = blockIdx.z;
    const float* A  = (zz == 0) ? q   : (zz == 1) ? k   : v;
    const float* W  = (zz == 0) ? w_q : (zz == 1) ? w_k : w_v;
    const float* bi = (zz == 0) ? b_q : (zz == 1) ? b_k : b_v;
    float*       o  = (zz == 0) ? oq  : (zz == 1) ? ok  : ov;
    gemm_body(A, W, bi, o, DMOD, NH * DKH, DKH, gsm);
}

// ---------------------------------------------------------------------------
// Scores v5: tile 64(q) x 64(k), 4 CTAs/SM (64-reg cap), minimized index ALU.
// MMA, then S staged through smem (aliasing Q) and fully coalesced
// gate/mask/exp/attn epilogue.  Row-sum partials via 16-lane shuffle.
// 256 threads (8 warps, 2m x 4n, warp 32x16).  grid (16, 16, 64).
// Dynamic smem: 2*64*68*4 = 34816 B.  4 CTAs/SM -> 139 KB smem.
// ---------------------------------------------------------------------------
#define SC_SMEM_BYTES (2 * 64 * 68 * 4)

__global__ void __launch_bounds__(256, 4)
scores_v5(const float* __restrict__ qh, const float* __restrict__ kh,
          const float* __restrict__ gate, const int* __restrict__ mask,
          float* __restrict__ attn, float* __restrict__ part)
{
    extern __shared__ float ssm[];
    float* Qs  = ssm;                  // 64 x 68 (later aliased as Ss)
    float* Ksm = ssm + 64 * 68;        // 64 x 68 (later aliased as redsh)

    const int t = threadIdx.x, lane = t & 31, w = t >> 5;
    const int wm = w >> 2, wn = w & 3;     // 2m x 4n warps, warp tile 32x16
    const int g = lane >> 2, tg = lane & 3;
    const int z = blockIdx.z, b = z >> 4;
    const int qBase = blockIdx.y * 64;
    const int kBase = blockIdx.x * 64;

    const float* Q  = qh + (size_t)z * (LS * DKH) + qBase * DKH;
    const float* Kp = kh + (size_t)z * (LS * DKH) + kBase * DKH;

    // stage Q (64x64) and K (64x64) via cp.async: 4 float4 each per thread
    {
        const int row = t >> 4, c = (t & 15) * 4;
        const int so = row * 68 + c;
        const int go = row * DKH + c;
#pragma unroll
        for (int i = 0; i < 4; i++) {
            cpa16(&Qs[so + i * 16 * 68], Q + go + i * 16 * DKH);
            cpa16(&Ksm[so + i * 16 * 68], Kp + go + i * 16 * DKH);
        }
    }
    cpa_commit();
    cpa_wait<0>();
    __syncthreads();

    float s[2][2][4];
#pragma unroll
    for (int mt = 0; mt < 2; mt++)
#pragma unroll
        for (int nt = 0; nt < 2; nt++)
#pragma unroll
            for (int i = 0; i < 4; i++) s[mt][nt][i] = 0.f;

    const int abase = (wm * 32 + g) * 68 + tg;
    const int bbase = (wn * 16 + g) * 68 + tg;
#pragma unroll
    for (int ks = 0; ks < 8; ks++) {
        const int kk = ks * 8;
        unsigned a[2][4], bf[2][2];
#pragma unroll
        for (int mt = 0; mt < 2; mt++) {
            const int r = abase + mt * (16 * 68) + kk;
            a[mt][0] = f2tf(Qs[r]);
            a[mt][1] = f2tf(Qs[r + 8 * 68]);
            a[mt][2] = f2tf(Qs[r + 4]);
            a[mt][3] = f2tf(Qs[r + 8 * 68 + 4]);
        }
#pragma unroll
        for (int nt = 0; nt < 2; nt++) {
            const int r = bbase + nt * (8 * 68) + kk;
            bf[nt][0] = f2tf(Ksm[r]);
            bf[nt][1] = f2tf(Ksm[r + 4]);
        }
#pragma unroll
        for (int mt = 0; mt < 2; mt++)
#pragma unroll
            for (int nt = 0; nt < 2; nt++)
                mma8(s[mt][nt][0], s[mt][nt][1], s[mt][nt][2], s[mt][nt][3],
                     a[mt][0], a[mt][1], a[mt][2], a[mt][3],
                     bf[nt][0], bf[nt][1]);
    }

    __syncthreads();   // Q/K smem reads done; safe to alias

    // stage S into smem (alias of Qs): 64 rows x 64 cols, stride 68
    float* Ss = Qs;
    {
        const int rb = wm * 32 + g;
        const int cb = wn * 16 + 2 * tg;
#pragma unroll
        for (int mt = 0; mt < 2; mt++) {
            const int ro = (rb + mt * 16) * 68;
#pragma unroll
            for (int nt = 0; nt < 2; nt++) {
                const int col = cb + nt * 8;
                *(float2*)&Ss[ro + col]          = make_float2(s[mt][nt][0], s[mt][nt][1]);
                *(float2*)&Ss[ro + 8 * 68 + col] = make_float2(s[mt][nt][2], s[mt][nt][3]);
            }
        }
    }
    __syncthreads();

    // coalesced epilogue: 1024 float4s, one row per 16 consecutive threads
    float* redsh = Ksm;
    {
        const int row0 = t >> 4, c4 = (t & 15) * 4;
        const size_t rowcol = (size_t)(qBase + row0) * LS + kBase + c4;
        const float* gp = gate + (size_t)z * (LS * LS) + rowcol;
        const int*   mp = mask + (size_t)b * (LS * LS) + rowcol;
        float*       ap = attn + (size_t)z * (LS * LS) + rowcol;
        int so = row0 * 68 + c4;
#pragma unroll
        for (int i = 0; i < 4; i++) {
            float4 sv = *(float4*)&Ss[so];
            float4 gv = *(const float4*)gp;
            int4   mv = *(const int4*)mp;
            float4 ev;
            ev.x = (mv.x > 0) ? 0.f : __expf(sv.x * 0.125f * gv.x);
            ev.y = (mv.y > 0) ? 0.f : __expf(sv.y * 0.125f * gv.y);
            ev.z = (mv.z > 0) ? 0.f : __expf(sv.z * 0.125f * gv.z);
            ev.w = (mv.w > 0) ? 0.f : __expf(sv.w * 0.125f * gv.w);
            *(float4*)ap = ev;
            float sum = (ev.x + ev.y) + (ev.z + ev.w);
            sum += __shfl_xor_sync(0xffffffffu, sum, 1);
            sum += __shfl_xor_sync(0xffffffffu, sum, 2);
            sum += __shfl_xor_sync(0xffffffffu, sum, 4);
            sum += __shfl_xor_sync(0xffffffffu, sum, 8);
            if ((lane & 15) == 0) redsh[row0 + 16 * i] = sum;
            so += 16 * 68;
            gp += 16 * LS; mp += 16 * LS; ap += 16 * LS;
        }
    }
    __syncthreads();
    if (t < 64)
        part[((size_t)z * LS + qBase + t) * 16 + blockIdx.x] = redsh[t];
}

// ---------------------------------------------------------------------------
// Reduce 16 partials -> 1/rowsum.  grid 256, block 256.
// ---------------------------------------------------------------------------
__global__ void reduce_inv(const float* __restrict__ part, float* __restrict__ invsum)
{
    const int i = blockIdx.x * 256 + threadIdx.x;   // 65536 rows
    float s = 0.f;
#pragma unroll
    for (int j = 0; j < 16; j++) s += part[(size_t)i * 16 + j];
    invsum[i] = 1.f / s;
}

// ---------------------------------------------------------------------------
// AV v4 (unchanged): tile 64x64, BK=64, P+V cp.async double-buffered,
// MMA on unnormalized P, ctx scaled at end, conditional attn write-back.
// ---------------------------------------------------------------------------
#define AV_SMEM_BYTES ((2 * 64 * 68 + 2 * 64 * 72) * 4)

__global__ void __launch_bounds__(256, 3)
av_v4(float* __restrict__ attn, const float* __restrict__ invsum,
      const float* __restrict__ vh, float* __restrict__ ctx, int write_attn)
{
    extern __shared__ float avsm[];
    float* Ps = avsm;                   // 2 x (64 x 68)
    float* Vs = avsm + 2 * 64 * 68;     // 2 x (64 x 72)
    __shared__ float invsh[64];

    const int t = threadIdx.x, lane = t & 31, w = t >> 5;
    const int wm = w >> 2, wn = w & 3;     // 2m x 4n warps, warp tile 32x16
    const int g = lane >> 2, tg = lane & 3;
    const int z = blockIdx.y, b = z >> 4, h = z & 15;
    const int rowBase = blockIdx.x * 64;

    float* P = attn + (size_t)z * LS * LS + (size_t)rowBase * LS;
    const float* V = vh + (size_t)z * LS * DVH;

    if (t < 64) invsh[t] = invsum[z * LS + rowBase + t];

    int lr[4], lc[4];
#pragma unroll
    for (int i = 0; i < 4; i++) {
        const int idx4 = t + 256 * i;
        lr[i] = idx4 >> 4;
        lc[i] = (idx4 & 15) * 4;
    }

    float c[2][2][4];
#pragma unroll
    for (int mt = 0; mt < 2; mt++)
#pragma unroll
        for (int nt = 0; nt < 2; nt++)
#pragma unroll
            for (int i = 0; i < 4; i++) c[mt][nt][i] = 0.f;

#pragma unroll
    for (int i = 0; i < 4; i++) {
        cpa16(&Ps[lr[i] * 68 + lc[i]], P + (size_t)lr[i] * LS + lc[i]);
        cpa16(&Vs[lr[i] * 72 + lc[i]], V + (size_t)lr[i] * DVH + lc[i]);
    }
    cpa_commit();

    for (int kt = 0; kt < 16; kt++) {
        const bool more = (kt + 1 < 16);
        if (more) {
            const int ko = (kt + 1) * 64;
            float* Pd = Ps + ((kt + 1) & 1) * (64 * 68);
            float* Vd = Vs + ((kt + 1) & 1) * (64 * 72);
#pragma unroll
            for (int i = 0; i < 4; i++) {
                cpa16(&Pd[lr[i] * 68 + lc[i]], P + (size_t)lr[i] * LS + ko + lc[i]);
                cpa16(&Vd[lr[i] * 72 + lc[i]], V + (size_t)(ko + lr[i]) * DVH + lc[i]);
            }
            cpa_commit();
            cpa_wait<1>();
        } else {
            cpa_wait<0>();
        }
        __syncthreads();

        const float* Pc = Ps + (kt & 1) * (64 * 68);
        const float* Vc = Vs + (kt & 1) * (64 * 72);

        if (write_attn) {
            const int ko = kt * 64;
#pragma unroll
            for (int i = 0; i < 4; i++) {
                float4 pv = *(const float4*)&Pc[lr[i] * 68 + lc[i]];
                const float iv = invsh[lr[i]];
                pv.x *= iv; pv.y *= iv; pv.z *= iv; pv.w *= iv;
                *(float4*)(P + (size_t)lr[i] * LS + ko + lc[i]) = pv;
            }
        }

#pragma unroll
        for (int ks = 0; ks < 8; ks++) {
            const int kk = ks * 8;
            unsigned a[2][4], bf[2][2];
#pragma unroll
            for (int mt = 0; mt < 2; mt++) {
                const int r = (wm * 32 + mt * 16 + g) * 68 + kk + tg;
                a[mt][0] = f2tf(Pc[r]);
                a[mt][1] = f2tf(Pc[r + 8 * 68]);
                a[mt][2] = f2tf(Pc[r + 4]);
                a[mt][3] = f2tf(Pc[r + 8 * 68 + 4]);
            }
#pragma unroll
            for (int nt = 0; nt < 2; nt++) {
                const int col = wn * 16 + nt * 8 + g;
                bf[nt][0] = f2tf(Vc[(kk + tg) * 72 + col]);
                bf[nt][1] = f2tf(Vc[(kk + tg + 4) * 72 + col]);
            }
#pragma unroll
            for (int mt = 0; mt < 2; mt++)
#pragma unroll
                for (int nt = 0; nt < 2; nt++)
                    mma8(c[mt][nt][0], c[mt][nt][1], c[mt][nt][2], c[mt][nt][3],
                         a[mt][0], a[mt][1], a[mt][2], a[mt][3],
                         bf[nt][0], bf[nt][1]);
        }
        __syncthreads();
    }

#pragma unroll
    for (int mt = 0; mt < 2; mt++) {
        const int lrow = wm * 32 + mt * 16 + g;
        const int rr = rowBase + lrow;
        const float iv0 = invsh[lrow], iv1 = invsh[lrow + 8];
#pragma unroll
        for (int nt = 0; nt < 2; nt++) {
            const int d = wn * 16 + nt * 8 + 2 * tg;
            const size_t dst = ((size_t)(b * LS + rr)) * DMOD + h * 64 + d;
            *(float2*)&ctx[dst]            = make_float2(c[mt][nt][0] * iv0, c[mt][nt][1] * iv0);
            *(float2*)&ctx[dst + 8 * DMOD] = make_float2(c[mt][nt][2] * iv1, c[mt][nt][3] * iv1);
        }
    }
}

// ---------------------------------------------------------------------------
// Residual + LayerNorm.  grid 4096, block 256.
// ---------------------------------------------------------------------------
__global__ void ln_kernel(const float* __restrict__ resid,
                          const float* __restrict__ gamma,
                          const float* __restrict__ beta,
                          const float* __restrict__ fcv,
                          float* __restrict__ out)
{
    __shared__ float red[256];
    const int r = blockIdx.x;
    const float* xf = fcv + (size_t)r * DMOD;
    const float* rz = resid + (size_t)r * DMOD;
    const int t = threadIdx.x;

    float v[4];
    float sum = 0.f;
#pragma unroll
    for (int j = 0; j < 4; j++) {
        v[j] = xf[t + 256 * j] + rz[t + 256 * j];
        sum += v[j];
    }
    red[t] = sum; __syncthreads();
    for (int s = 128; s > 0; s >>= 1) {
        if (t < s) red[t] += red[t + s];
        __syncthreads();
    }
    const float mu = red[0] * (1.f / DMOD);
    __syncthreads();

    float vs = 0.f;
#pragma unroll
    for (int j = 0; j < 4; j++) {
        const float d = v[j] - mu;
        vs += d * d;
    }
    red[t] = vs; __syncthreads();
    for (int s = 128; s > 0; s >>= 1) {
        if (t < s) red[t] += red[t + s];
        __syncthreads();
    }
    const float var = red[0] * (1.f / DMOD);
    const float inv = rsqrtf(var + 1e-5f);
#pragma unroll
    for (int j = 0; j < 4; j++) {
        const int cc = t + 256 * j;
        out[(size_t)r * DMOD + cc] = (v[j] - mu) * inv * gamma[cc] + beta[cc];
    }
}

// ---------------------------------------------------------------------------
extern "C" void kernel_launch(void* const* d_in, const int* in_sizes, int n_in,
                              void* d_out, int out_size)
{
    const float* q    = (const float*)d_in[0];
    const float* k    = (const float*)d_in[1];
    const float* v    = (const float*)d_in[2];
    const int*   mask = (const int*)  d_in[3];
    const float* gate = (const float*)d_in[4];
    const float* w_q  = (const float*)d_in[5];
    const float* b_q  = (const float*)d_in[6];
    const float* w_k  = (const float*)d_in[7];
    const float* b_k  = (const float*)d_in[8];
    const float* w_v  = (const float*)d_in[9];
    const float* b_v  = (const float*)d_in[10];
    const float* w_fc = (const float*)d_in[11];
    const float* b_fc = (const float*)d_in[12];
    const float* ln_g = (const float*)d_in[13];
    const float* ln_b = (const float*)d_in[14];
    float* out = (float*)d_out;

    float *p_qh, *p_kh, *p_vh, *p_ctx, *p_fc, *p_part, *p_inv, *p_attn_s, *p_outs;
    cudaGetSymbolAddress((void**)&p_qh,     g_qh);
    cudaGetSymbolAddress((void**)&p_kh,     g_kh);
    cudaGetSymbolAddress((void**)&p_vh,     g_vh);
    cudaGetSymbolAddress((void**)&p_ctx,    g_ctx);
    cudaGetSymbolAddress((void**)&p_fc,     g_fc);
    cudaGetSymbolAddress((void**)&p_part,   g_part);
    cudaGetSymbolAddress((void**)&p_inv,    g_invsum);
    cudaGetSymbolAddress((void**)&p_attn_s, g_attn);
    cudaGetSymbolAddress((void**)&p_outs,   g_outs);

    // Reference returns (out, attn).  Resolve destinations from out_size.
    float* attn_ptr;
    float* out_ptr;
    const long long osz = (long long)out_size;
    if (osz >= OUT_ELEMS + ATT_ELEMS) {        // concatenated tuple
        out_ptr  = out;
        attn_ptr = out + OUT_ELEMS;
    } else if (osz >= ATT_ELEMS) {             // attn only
        out_ptr  = p_outs;
        attn_ptr = out;
    } else {                                   // out only
        out_ptr  = out;
        attn_ptr = p_attn_s;
    }
    const int write_attn = (attn_ptr != p_attn_s) ? 1 : 0;

    // opt in to >48KB dynamic smem (idempotent)
    cudaFuncSetAttribute(gemm_v2, cudaFuncAttributeMaxDynamicSharedMemorySize,
                         GEMM_SMEM_BYTES);
    cudaFuncSetAttribute(gemm_qkv, cudaFuncAttributeMaxDynamicSharedMemorySize,
                         GEMM_SMEM_BYTES);
    cudaFuncSetAttribute(av_v4, cudaFuncAttributeMaxDynamicSharedMemorySize,
                         AV_SMEM_BYTES);

    // 1) QKV projections (merged: one launch, grid.z selects q/k/v)
    gemm_qkv<<<dim3(16, 32, 3), 256, GEMM_SMEM_BYTES>>>(
        q, k, v, w_q, w_k, w_v, b_q, b_k, b_v, p_qh, p_kh, p_vh);

    // 2) Scores + gate/mask + exp + partial row sums (unnormalized attn)
    scores_v5<<<dim3(16, 16, ZH), 256, SC_SMEM_BYTES>>>(p_qh, p_kh, gate, mask, attn_ptr, p_part);

    // 3) partials -> 1/rowsum
    reduce_inv<<<256, 256>>>(p_part, p_inv);

    // 4) AV: MMA unnormalized P, scale ctx; conditional normalized attn write
    av_v4<<<dim3(16, ZH), 256, AV_SMEM_BYTES>>>(attn_ptr, p_inv, p_vh, p_ctx, write_attn);

    // 5) FC projection
    gemm_v2<<<dim3(16, 32), 256, GEMM_SMEM_BYTES>>>(p_ctx, w_fc, b_fc, p_fc, DMOD, DMOD, DMOD);

    // 6) Residual + LayerNorm -> final out
    ln_kernel<<<4096, 256>>>(q, ln_g, ln_b, p_fc, out_ptr);
}

// round 11
// speedup vs baseline: 1.5292x; 1.0270x over previous
#include <cuda_runtime.h>
#include <math.h>

// Problem constants
#define BB 4
#define LS 1024
#define DMOD 1024
#define NH 16
#define DKH 64
#define DVH 64
#define ZH (BB * NH)

#define OUT_ELEMS ((long long)BB * LS * DMOD)            // 4194304
#define ATT_ELEMS ((long long)ZH * LS * LS)              // 67108864

// -------------------- scratch (device globals; no allocation allowed) ------
__device__ float g_qh[ZH * LS * DKH];        // [B,H,L,DK]
__device__ float g_kh[ZH * LS * DKH];
__device__ float g_vh[ZH * LS * DVH];
__device__ float g_ctx[BB * LS * NH * DVH];  // [B,L,H*DV]
__device__ float g_fc[BB * LS * DMOD];       // pre-LN fc output
__device__ float g_part[(size_t)ZH * LS * 16]; // per-(z,row) partial exp sums
__device__ float g_invsum[ZH * LS];          // 1 / rowsum
__device__ float g_attn[(size_t)ZH * LS * LS]; // attn scratch (fallback dest)
__device__ float g_outs[BB * LS * DMOD];     // fallback out sink

// ---------------------------------------------------------------------------
// helpers
// ---------------------------------------------------------------------------
__device__ __forceinline__ unsigned f2tf(float f) {
    unsigned r;
    asm("cvt.rna.tf32.f32 %0, %1;" : "=r"(r) : "f"(f));
    return r;
}

__device__ __forceinline__ void mma8(float& c0, float& c1, float& c2, float& c3,
                                     unsigned a0, unsigned a1, unsigned a2, unsigned a3,
                                     unsigned b0, unsigned b1) {
    asm volatile(
        "mma.sync.aligned.m16n8k8.row.col.f32.tf32.tf32.f32 "
        "{%0,%1,%2,%3}, {%4,%5,%6,%7}, {%8,%9}, {%0,%1,%2,%3};\n"
        : "+f"(c0), "+f"(c1), "+f"(c2), "+f"(c3)
        : "r"(a0), "r"(a1), "r"(a2), "r"(a3), "r"(b0), "r"(b1));
}

__device__ __forceinline__ void cpa16(void* s, const void* g) {
    asm volatile("cp.async.cg.shared.global [%0], [%1], 16;\n"
        :: "r"((unsigned)__cvta_generic_to_shared(s)), "l"(g) : "memory");
}
__device__ __forceinline__ void cpa_commit() {
    asm volatile("cp.async.commit_group;\n" ::: "memory");
}
template <int N> __device__ __forceinline__ void cpa_wait() {
    asm volatile("cp.async.wait_group %0;\n" :: "n"(N) : "memory");
}

// ---------------------------------------------------------------------------
// TF32 NT GEMM + bias, cp.async double-buffered, 3 CTAs/SM.
// Tile 128(m) x 64(n), BK=32, 256 threads (8 warps, 4m x 2n, warp 32x32).
// ---------------------------------------------------------------------------
#define GEMM_SMEM_BYTES ((2 * 128 * 36 + 2 * 64 * 36) * 4)

__device__ __forceinline__ void gemm_body(
    const float* __restrict__ A, const float* __restrict__ W,
    const float* __restrict__ bias, float* __restrict__ out,
    int K, int N, int Dhead, float* gsm)
{
    float* As = gsm;
    float* Ws = gsm + 2 * 128 * 36;

    const int t = threadIdx.x, lane = t & 31, w = t >> 5;
    const int wm = w >> 1, wn = w & 1;
    const int g = lane >> 2, tg = lane & 3;
    const int rowBase = blockIdx.y * 128;
    const int colBase = blockIdx.x * 64;

    const float* Ab = A + (size_t)rowBase * K;
    const float* Wb = W + (size_t)colBase * K;

    float c[2][4][4];
#pragma unroll
    for (int mt = 0; mt < 2; mt++)
#pragma unroll
        for (int nt = 0; nt < 4; nt++)
#pragma unroll
            for (int i = 0; i < 4; i++) c[mt][nt][i] = 0.f;

    const int nk = K >> 5;

    {
#pragma unroll
        for (int i = 0; i < 4; i++) {
            const int idx4 = t + 256 * i;
            const int row = idx4 >> 3, c4 = (idx4 & 7) * 4;
            cpa16(&As[row * 36 + c4], Ab + (size_t)row * K + c4);
        }
#pragma unroll
        for (int i = 0; i < 2; i++) {
            const int idx4 = t + 256 * i;
            const int row = idx4 >> 3, c4 = (idx4 & 7) * 4;
            cpa16(&Ws[row * 36 + c4], Wb + (size_t)row * K + c4);
        }
        cpa_commit();
    }

    for (int kt = 0; kt < nk; kt++) {
        if (kt + 1 < nk) {
            float* Ad = As + ((kt + 1) & 1) * (128 * 36);
            float* Wd = Ws + ((kt + 1) & 1) * (64 * 36);
            const int ko = (kt + 1) * 32;
#pragma unroll
            for (int i = 0; i < 4; i++) {
                const int idx4 = t + 256 * i;
                const int row = idx4 >> 3, c4 = (idx4 & 7) * 4;
                cpa16(&Ad[row * 36 + c4], Ab + (size_t)row * K + ko + c4);
            }
#pragma unroll
            for (int i = 0; i < 2; i++) {
                const int idx4 = t + 256 * i;
                const int row = idx4 >> 3, c4 = (idx4 & 7) * 4;
                cpa16(&Wd[row * 36 + c4], Wb + (size_t)row * K + ko + c4);
            }
            cpa_commit();
            cpa_wait<1>();
        } else {
            cpa_wait<0>();
        }
        __syncthreads();

        const float* Ac = As + (kt & 1) * (128 * 36);
        const float* Wc = Ws + (kt & 1) * (64 * 36);
#pragma unroll
        for (int ks = 0; ks < 4; ks++) {
            const int kk = ks * 8;
            unsigned a[2][4], bf[4][2];
#pragma unroll
            for (int mt = 0; mt < 2; mt++) {
                const int r = (wm * 32 + mt * 16 + g) * 36 + kk + tg;
                a[mt][0] = f2tf(Ac[r]);
                a[mt][1] = f2tf(Ac[r + 8 * 36]);
                a[mt][2] = f2tf(Ac[r + 4]);
                a[mt][3] = f2tf(Ac[r + 8 * 36 + 4]);
            }
#pragma unroll
            for (int nt = 0; nt < 4; nt++) {
                const int r = (wn * 32 + nt * 8 + g) * 36 + kk + tg;
                bf[nt][0] = f2tf(Wc[r]);
                bf[nt][1] = f2tf(Wc[r + 4]);
            }
#pragma unroll
            for (int mt = 0; mt < 2; mt++)
#pragma unroll
                for (int nt = 0; nt < 4; nt++)
                    mma8(c[mt][nt][0], c[mt][nt][1], c[mt][nt][2], c[mt][nt][3],
                         a[mt][0], a[mt][1], a[mt][2], a[mt][3],
                         bf[nt][0], bf[nt][1]);
        }
        __syncthreads();
    }

    const int H = N / Dhead;
#pragma unroll
    for (int mt = 0; mt < 2; mt++) {
        const int rr = rowBase + wm * 32 + mt * 16 + g;
        const int b_ = rr >> 10, l = rr & 1023;
#pragma unroll
        for (int nt = 0; nt < 4; nt++) {
            const int cc = colBase + wn * 32 + nt * 8 + 2 * tg;
            const int h = cc / Dhead, d = cc % Dhead;
            const size_t dst = (((size_t)(b_ * H + h)) * LS + l) * Dhead + d;
            const float b0 = bias[cc], b1 = bias[cc + 1];
            *(float2*)&out[dst]             = make_float2(c[mt][nt][0] + b0, c[mt][nt][1] + b1);
            *(float2*)&out[dst + 8 * Dhead] = make_float2(c[mt][nt][2] + b0, c[mt][nt][3] + b1);
        }
    }
}

__global__ void __launch_bounds__(256, 3)
gemm_v2(const float* __restrict__ A, const float* __restrict__ W,
        const float* __restrict__ bias, float* __restrict__ out,
        int K, int N, int Dhead)
{
    extern __shared__ float gsm[];
    gemm_body(A, W, bias, out, K, N, Dhead, gsm);
}

__global__ void __launch_bounds__(256, 3)
gemm_qkv(const float* __restrict__ q, const float* __restrict__ k,
         const float* __restrict__ v,
         const float* __restrict__ w_q, const float* __restrict__ w_k,
         const float* __restrict__ w_v,
         const float* __restrict__ b_q, const float* __restrict__ b_k,
         const float* __restrict__ b_v,
         float* __restrict__ oq, float* __restrict__ ok, float* __restrict__ ov)
{
    extern __shared__ float gsm[];
    const int zz = blockIdx.z;
    const float* A  = (zz == 0) ? q   : (zz == 1) ? k   : v;
    const float* W  = (zz == 0) ? w_q : (zz == 1) ? w_k : w_v;
    const float* bi = (zz == 0) ? b_q : (zz == 1) ? b_k : b_v;
    float*       o  = (zz == 0) ? oq  : (zz == 1) ? ok  : ov;
    gemm_body(A, W, bi, o, DMOD, NH * DKH, DKH, gsm);
}

// ---------------------------------------------------------------------------
// Scores v5 (round 9 exact): tile 64x64, 4 CTAs/SM, coalesced epilogue,
// writes unnormalized exp attn + row-sum partials.
// ---------------------------------------------------------------------------
#define SC_SMEM_BYTES (2 * 64 * 68 * 4)

__global__ void __launch_bounds__(256, 4)
scores_v5(const float* __restrict__ qh, const float* __restrict__ kh,
          const float* __restrict__ gate, const int* __restrict__ mask,
          float* __restrict__ attn, float* __restrict__ part)
{
    extern __shared__ float ssm[];
    float* Qs  = ssm;                  // 64 x 68 (later aliased as Ss)
    float* Ksm = ssm + 64 * 68;        // 64 x 68 (later aliased as redsh)

    const int t = threadIdx.x, lane = t & 31, w = t >> 5;
    const int wm = w >> 2, wn = w & 3;     // 2m x 4n warps, warp tile 32x16
    const int g = lane >> 2, tg = lane & 3;
    const int z = blockIdx.z, b = z >> 4;
    const int qBase = blockIdx.y * 64;
    const int kBase = blockIdx.x * 64;

    const float* Q  = qh + (size_t)z * (LS * DKH) + qBase * DKH;
    const float* Kp = kh + (size_t)z * (LS * DKH) + kBase * DKH;

    {
        const int row = t >> 4, c = (t & 15) * 4;
        const int so = row * 68 + c;
        const int go = row * DKH + c;
#pragma unroll
        for (int i = 0; i < 4; i++) {
            cpa16(&Qs[so + i * 16 * 68], Q + go + i * 16 * DKH);
            cpa16(&Ksm[so + i * 16 * 68], Kp + go + i * 16 * DKH);
        }
    }
    cpa_commit();
    cpa_wait<0>();
    __syncthreads();

    float s[2][2][4];
#pragma unroll
    for (int mt = 0; mt < 2; mt++)
#pragma unroll
        for (int nt = 0; nt < 2; nt++)
#pragma unroll
            for (int i = 0; i < 4; i++) s[mt][nt][i] = 0.f;

    const int abase = (wm * 32 + g) * 68 + tg;
    const int bbase = (wn * 16 + g) * 68 + tg;
#pragma unroll
    for (int ks = 0; ks < 8; ks++) {
        const int kk = ks * 8;
        unsigned a[2][4], bf[2][2];
#pragma unroll
        for (int mt = 0; mt < 2; mt++) {
            const int r = abase + mt * (16 * 68) + kk;
            a[mt][0] = f2tf(Qs[r]);
            a[mt][1] = f2tf(Qs[r + 8 * 68]);
            a[mt][2] = f2tf(Qs[r + 4]);
            a[mt][3] = f2tf(Qs[r + 8 * 68 + 4]);
        }
#pragma unroll
        for (int nt = 0; nt < 2; nt++) {
            const int r = bbase + nt * (8 * 68) + kk;
            bf[nt][0] = f2tf(Ksm[r]);
            bf[nt][1] = f2tf(Ksm[r + 4]);
        }
#pragma unroll
        for (int mt = 0; mt < 2; mt++)
#pragma unroll
            for (int nt = 0; nt < 2; nt++)
                mma8(s[mt][nt][0], s[mt][nt][1], s[mt][nt][2], s[mt][nt][3],
                     a[mt][0], a[mt][1], a[mt][2], a[mt][3],
                     bf[nt][0], bf[nt][1]);
    }

    __syncthreads();   // Q/K smem reads done; safe to alias

    float* Ss = Qs;
    {
        const int rb = wm * 32 + g;
        const int cb = wn * 16 + 2 * tg;
#pragma unroll
        for (int mt = 0; mt < 2; mt++) {
            const int ro = (rb + mt * 16) * 68;
#pragma unroll
            for (int nt = 0; nt < 2; nt++) {
                const int col = cb + nt * 8;
                *(float2*)&Ss[ro + col]          = make_float2(s[mt][nt][0], s[mt][nt][1]);
                *(float2*)&Ss[ro + 8 * 68 + col] = make_float2(s[mt][nt][2], s[mt][nt][3]);
            }
        }
    }
    __syncthreads();

    float* redsh = Ksm;
    {
        const int row0 = t >> 4, c4 = (t & 15) * 4;
        const size_t rowcol = (size_t)(qBase + row0) * LS + kBase + c4;
        const float* gp = gate + (size_t)z * (LS * LS) + rowcol;
        const int*   mp = mask + (size_t)b * (LS * LS) + rowcol;
        float*       ap = attn + (size_t)z * (LS * LS) + rowcol;
        int so = row0 * 68 + c4;
#pragma unroll
        for (int i = 0; i < 4; i++) {
            float4 sv = *(float4*)&Ss[so];
            float4 gv = *(const float4*)gp;
            int4   mv = *(const int4*)mp;
            float4 ev;
            ev.x = (mv.x > 0) ? 0.f : __expf(sv.x * 0.125f * gv.x);
            ev.y = (mv.y > 0) ? 0.f : __expf(sv.y * 0.125f * gv.y);
            ev.z = (mv.z > 0) ? 0.f : __expf(sv.z * 0.125f * gv.z);
            ev.w = (mv.w > 0) ? 0.f : __expf(sv.w * 0.125f * gv.w);
            *(float4*)ap = ev;
            float sum = (ev.x + ev.y) + (ev.z + ev.w);
            sum += __shfl_xor_sync(0xffffffffu, sum, 1);
            sum += __shfl_xor_sync(0xffffffffu, sum, 2);
            sum += __shfl_xor_sync(0xffffffffu, sum, 4);
            sum += __shfl_xor_sync(0xffffffffu, sum, 8);
            if ((lane & 15) == 0) redsh[row0 + 16 * i] = sum;
            so += 16 * 68;
            gp += 16 * LS; mp += 16 * LS; ap += 16 * LS;
        }
    }
    __syncthreads();
    if (t < 64)
        part[((size_t)z * LS + qBase + t) * 16 + blockIdx.x] = redsh[t];
}

// ---------------------------------------------------------------------------
// Reduce 16 partials -> 1/rowsum.  grid 256, block 256.
// ---------------------------------------------------------------------------
__global__ void reduce_inv(const float* __restrict__ part, float* __restrict__ invsum)
{
    const int i = blockIdx.x * 256 + threadIdx.x;   // 65536 rows
    float s = 0.f;
#pragma unroll
    for (int j = 0; j < 16; j++) s += part[(size_t)i * 16 + j];
    invsum[i] = 1.f / s;
}

// ---------------------------------------------------------------------------
// AV v4 (round 9 exact): tile 64x64, BK=64, P+V cp.async double-buffered,
// MMA on unnormalized P, ctx scaled at end, conditional attn write-back.
// ---------------------------------------------------------------------------
#define AV_SMEM_BYTES ((2 * 64 * 68 + 2 * 64 * 72) * 4)

__global__ void __launch_bounds__(256, 3)
av_v4(float* __restrict__ attn, const float* __restrict__ invsum,
      const float* __restrict__ vh, float* __restrict__ ctx, int write_attn)
{
    extern __shared__ float avsm[];
    float* Ps = avsm;                   // 2 x (64 x 68)
    float* Vs = avsm + 2 * 64 * 68;     // 2 x (64 x 72)
    __shared__ float invsh[64];

    const int t = threadIdx.x, lane = t & 31, w = t >> 5;
    const int wm = w >> 2, wn = w & 3;     // 2m x 4n warps, warp tile 32x16
    const int g = lane >> 2, tg = lane & 3;
    const int z = blockIdx.y, b = z >> 4, h = z & 15;
    const int rowBase = blockIdx.x * 64;

    float* P = attn + (size_t)z * LS * LS + (size_t)rowBase * LS;
    const float* V = vh + (size_t)z * LS * DVH;

    if (t < 64) invsh[t] = invsum[z * LS + rowBase + t];

    int lr[4], lc[4];
#pragma unroll
    for (int i = 0; i < 4; i++) {
        const int idx4 = t + 256 * i;
        lr[i] = idx4 >> 4;
        lc[i] = (idx4 & 15) * 4;
    }

    float c[2][2][4];
#pragma unroll
    for (int mt = 0; mt < 2; mt++)
#pragma unroll
        for (int nt = 0; nt < 2; nt++)
#pragma unroll
            for (int i = 0; i < 4; i++) c[mt][nt][i] = 0.f;

#pragma unroll
    for (int i = 0; i < 4; i++) {
        cpa16(&Ps[lr[i] * 68 + lc[i]], P + (size_t)lr[i] * LS + lc[i]);
        cpa16(&Vs[lr[i] * 72 + lc[i]], V + (size_t)lr[i] * DVH + lc[i]);
    }
    cpa_commit();

    for (int kt = 0; kt < 16; kt++) {
        const bool more = (kt + 1 < 16);
        if (more) {
            const int ko = (kt + 1) * 64;
            float* Pd = Ps + ((kt + 1) & 1) * (64 * 68);
            float* Vd = Vs + ((kt + 1) & 1) * (64 * 72);
#pragma unroll
            for (int i = 0; i < 4; i++) {
                cpa16(&Pd[lr[i] * 68 + lc[i]], P + (size_t)lr[i] * LS + ko + lc[i]);
                cpa16(&Vd[lr[i] * 72 + lc[i]], V + (size_t)(ko + lr[i]) * DVH + lc[i]);
            }
            cpa_commit();
            cpa_wait<1>();
        } else {
            cpa_wait<0>();
        }
        __syncthreads();

        const float* Pc = Ps + (kt & 1) * (64 * 68);
        const float* Vc = Vs + (kt & 1) * (64 * 72);

        if (write_attn) {
            const int ko = kt * 64;
#pragma unroll
            for (int i = 0; i < 4; i++) {
                float4 pv = *(const float4*)&Pc[lr[i] * 68 + lc[i]];
                const float iv = invsh[lr[i]];
                pv.x *= iv; pv.y *= iv; pv.z *= iv; pv.w *= iv;
                *(float4*)(P + (size_t)lr[i] * LS + ko + lc[i]) = pv;
            }
        }

#pragma unroll
        for (int ks = 0; ks < 8; ks++) {
            const int kk = ks * 8;
            unsigned a[2][4], bf[2][2];
#pragma unroll
            for (int mt = 0; mt < 2; mt++) {
                const int r = (wm * 32 + mt * 16 + g) * 68 + kk + tg;
                a[mt][0] = f2tf(Pc[r]);
                a[mt][1] = f2tf(Pc[r + 8 * 68]);
                a[mt][2] = f2tf(Pc[r + 4]);
                a[mt][3] = f2tf(Pc[r + 8 * 68 + 4]);
            }
#pragma unroll
            for (int nt = 0; nt < 2; nt++) {
                const int col = wn * 16 + nt * 8 + g;
                bf[nt][0] = f2tf(Vc[(kk + tg) * 72 + col]);
                bf[nt][1] = f2tf(Vc[(kk + tg + 4) * 72 + col]);
            }
#pragma unroll
            for (int mt = 0; mt < 2; mt++)
#pragma unroll
                for (int nt = 0; nt < 2; nt++)
                    mma8(c[mt][nt][0], c[mt][nt][1], c[mt][nt][2], c[mt][nt][3],
                         a[mt][0], a[mt][1], a[mt][2], a[mt][3],
                         bf[nt][0], bf[nt][1]);
        }
        __syncthreads();
    }

#pragma unroll
    for (int mt = 0; mt < 2; mt++) {
        const int lrow = wm * 32 + mt * 16 + g;
        const int rr = rowBase + lrow;
        const float iv0 = invsh[lrow], iv1 = invsh[lrow + 8];
#pragma unroll
        for (int nt = 0; nt < 2; nt++) {
            const int d = wn * 16 + nt * 8 + 2 * tg;
            const size_t dst = ((size_t)(b * LS + rr)) * DMOD + h * 64 + d;
            *(float2*)&ctx[dst]            = make_float2(c[mt][nt][0] * iv0, c[mt][nt][1] * iv0);
            *(float2*)&ctx[dst + 8 * DMOD] = make_float2(c[mt][nt][2] * iv1, c[mt][nt][3] * iv1);
        }
    }
}

// ---------------------------------------------------------------------------
// Residual + LayerNorm.  grid 4096, block 256.
// ---------------------------------------------------------------------------
__global__ void ln_kernel(const float* __restrict__ resid,
                          const float* __restrict__ gamma,
                          const float* __restrict__ beta,
                          const float* __restrict__ fcv,
                          float* __restrict__ out)
{
    __shared__ float red[256];
    const int r = blockIdx.x;
    const float* xf = fcv + (size_t)r * DMOD;
    const float* rz = resid + (size_t)r * DMOD;
    const int t = threadIdx.x;

    float v[4];
    float sum = 0.f;
#pragma unroll
    for (int j = 0; j < 4; j++) {
        v[j] = xf[t + 256 * j] + rz[t + 256 * j];
        sum += v[j];
    }
    red[t] = sum; __syncthreads();
    for (int s = 128; s > 0; s >>= 1) {
        if (t < s) red[t] += red[t + s];
        __syncthreads();
    }
    const float mu = red[0] * (1.f / DMOD);
    __syncthreads();

    float vs = 0.f;
#pragma unroll
    for (int j = 0; j < 4; j++) {
        const float d = v[j] - mu;
        vs += d * d;
    }
    red[t] = vs; __syncthreads();
    for (int s = 128; s > 0; s >>= 1) {
        if (t < s) red[t] += red[t + s];
        __syncthreads();
    }
    const float var = red[0] * (1.f / DMOD);
    const float inv = rsqrtf(var + 1e-5f);
#pragma unroll
    for (int j = 0; j < 4; j++) {
        const int cc = t + 256 * j;
        out[(size_t)r * DMOD + cc] = (v[j] - mu) * inv * gamma[cc] + beta[cc];
    }
}

// ---------------------------------------------------------------------------
extern "C" void kernel_launch(void* const* d_in, const int* in_sizes, int n_in,
                              void* d_out, int out_size)
{
    const float* q    = (const float*)d_in[0];
    const float* k    = (const float*)d_in[1];
    const float* v    = (const float*)d_in[2];
    const int*   mask = (const int*)  d_in[3];
    const float* gate = (const float*)d_in[4];
    const float* w_q  = (const float*)d_in[5];
    const float* b_q  = (const float*)d_in[6];
    const float* w_k  = (const float*)d_in[7];
    const float* b_k  = (const float*)d_in[8];
    const float* w_v  = (const float*)d_in[9];
    const float* b_v  = (const float*)d_in[10];
    const float* w_fc = (const float*)d_in[11];
    const float* b_fc = (const float*)d_in[12];
    const float* ln_g = (const float*)d_in[13];
    const float* ln_b = (const float*)d_in[14];
    float* out = (float*)d_out;

    float *p_qh, *p_kh, *p_vh, *p_ctx, *p_fc, *p_part, *p_inv, *p_attn_s, *p_outs;
    cudaGetSymbolAddress((void**)&p_qh,     g_qh);
    cudaGetSymbolAddress((void**)&p_kh,     g_kh);
    cudaGetSymbolAddress((void**)&p_vh,     g_vh);
    cudaGetSymbolAddress((void**)&p_ctx,    g_ctx);
    cudaGetSymbolAddress((void**)&p_fc,     g_fc);
    cudaGetSymbolAddress((void**)&p_part,   g_part);
    cudaGetSymbolAddress((void**)&p_inv,    g_invsum);
    cudaGetSymbolAddress((void**)&p_attn_s, g_attn);
    cudaGetSymbolAddress((void**)&p_outs,   g_outs);

    // Reference returns (out, attn).  Resolve destinations from out_size.
    float* attn_ptr;
    float* out_ptr;
    const long long osz = (long long)out_size;
    if (osz >= OUT_ELEMS + ATT_ELEMS) {        // concatenated tuple
        out_ptr  = out;
        attn_ptr = out + OUT_ELEMS;
    } else if (osz >= ATT_ELEMS) {             // attn only
        out_ptr  = p_outs;
        attn_ptr = out;
    } else {                                   // out only
        out_ptr  = out;
        attn_ptr = p_attn_s;
    }
    const int write_attn = (attn_ptr != p_attn_s) ? 1 : 0;

    // opt in to >48KB dynamic smem (idempotent)
    cudaFuncSetAttribute(gemm_v2, cudaFuncAttributeMaxDynamicSharedMemorySize,
                         GEMM_SMEM_BYTES);
    cudaFuncSetAttribute(gemm_qkv, cudaFuncAttributeMaxDynamicSharedMemorySize,
                         GEMM_SMEM_BYTES);
    cudaFuncSetAttribute(av_v4, cudaFuncAttributeMaxDynamicSharedMemorySize,
                         AV_SMEM_BYTES);

    // 1) QKV projections (merged: one launch, grid.z selects q/k/v)
    gemm_qkv<<<dim3(16, 32, 3), 256, GEMM_SMEM_BYTES>>>(
        q, k, v, w_q, w_k, w_v, b_q, b_k, b_v, p_qh, p_kh, p_vh);

    // 2) Scores + gate/mask + exp + partial row sums (unnormalized attn)
    scores_v5<<<dim3(16, 16, ZH), 256, SC_SMEM_BYTES>>>(p_qh, p_kh, gate, mask, attn_ptr, p_part);

    // 3) partials -> 1/rowsum
    reduce_inv<<<256, 256>>>(p_part, p_inv);

    // 4) AV: MMA unnormalized P, scale ctx; conditional normalized attn write
    av_v4<<<dim3(16, ZH), 256, AV_SMEM_BYTES>>>(attn_ptr, p_inv, p_vh, p_ctx, write_attn);

    // 5) FC projection
    gemm_v2<<<dim3(16, 32), 256, GEMM_SMEM_BYTES>>>(p_ctx, w_fc, b_fc, p_fc, DMOD, DMOD, DMOD);

    // 6) Residual + LayerNorm -> final out
    ln_kernel<<<4096, 256>>>(q, ln_g, ln_b, p_fc, out_ptr);
}